// round 1
// baseline (speedup 1.0000x reference)
#include <cuda_runtime.h>
#include <math.h>
#include <float.h>

#define NTHREADS 256
#define TOK 32        // tokens per CTA
#define DIM 256       // D
#define E1  512       // 2*D
#define NMEM 50
#define KNN 5
#define KC 16         // k-chunk staged in smem
#define WST 132       // padded row stride of W staging tile (floats)

// smem layout (floats)
#define A_OFF 0                 // Xs / Fs  [32][256]          = 8192
#define B_OFF 8192              // Hs [32][512] / Ms [50][256] = 16384
#define C_OFF 24576             // Wt [16][132] = 2112 ; alias: dists[32][50], fsq[32], msq[50]
#define SMEM_FLOATS 26688
#define SMEM_BYTES (SMEM_FLOATS * 4)

__device__ __forceinline__ float warp_sum(float v) {
    v += __shfl_xor_sync(0xffffffffu, v, 16);
    v += __shfl_xor_sync(0xffffffffu, v, 8);
    v += __shfl_xor_sync(0xffffffffu, v, 4);
    v += __shfl_xor_sync(0xffffffffu, v, 2);
    v += __shfl_xor_sync(0xffffffffu, v, 1);
    return v;
}

__global__ __launch_bounds__(NTHREADS, 2)
void ipm_fused(const float* __restrict__ X, const float* __restrict__ Mem,
               const float* __restrict__ W1, const float* __restrict__ b1,
               const float* __restrict__ W2, const float* __restrict__ b2,
               const float* __restrict__ lng, const float* __restrict__ lnb,
               float* __restrict__ out, int ntok)
{
    extern __shared__ float smem[];
    float* As    = smem + A_OFF;          // X tile, later LayerNorm'd features
    float* Bs    = smem + B_OFF;          // H tile, later memory patterns
    float* Wt    = smem + C_OFF;          // weight staging tile
    float* dists = smem + C_OFF;          // [32][50]  (alias, used after GEMMs)
    float* fsq   = smem + C_OFF + 1600;   // [32]
    float* msq   = smem + C_OFF + 1632;   // [50]

    const int tid  = threadIdx.x;
    const int lane = tid & 31;
    const int w    = tid >> 5;            // warp id 0..7
    const int te   = lane;                // e-group within tile
    const int t0   = w * 4;               // this warp's 4 tokens
    const int tok0 = blockIdx.x * TOK;

    // ---------------- Phase 0: load X tile (float4) ----------------
    #pragma unroll
    for (int q = tid; q < TOK * DIM / 4; q += NTHREADS) {
        int t = q >> 6;          // 64 float4 per row
        int c = q & 63;
        int tg = tok0 + t; if (tg >= ntok) tg = ntok - 1;
        *reinterpret_cast<float4*>(&As[t * DIM + c * 4]) =
            *reinterpret_cast<const float4*>(&X[(long)tg * DIM + c * 4]);
    }

    // ---------------- Phase 1: H = relu(X @ W1 + b1) -> Bs ----------------
    for (int et = 0; et < 4; et++) {
        const int e0 = et * 128;
        float4 bini = *reinterpret_cast<const float4*>(&b1[e0 + te * 4]);
        float acc[4][4];
        #pragma unroll
        for (int i = 0; i < 4; i++) {
            acc[i][0] = bini.x; acc[i][1] = bini.y; acc[i][2] = bini.z; acc[i][3] = bini.w;
        }
        for (int k0 = 0; k0 < DIM; k0 += KC) {
            __syncthreads();
            #pragma unroll
            for (int q = tid; q < KC * 32; q += NTHREADS) {
                int kk = q >> 5, c = q & 31;
                *reinterpret_cast<float4*>(&Wt[kk * WST + c * 4]) =
                    *reinterpret_cast<const float4*>(&W1[(k0 + kk) * E1 + e0 + c * 4]);
            }
            __syncthreads();
            #pragma unroll
            for (int kk = 0; kk < KC; kk++) {
                float4 bv = *reinterpret_cast<float4*>(&Wt[kk * WST + te * 4]);
                #pragma unroll
                for (int i = 0; i < 4; i++) {
                    float a = As[(t0 + i) * DIM + k0 + kk];
                    acc[i][0] += a * bv.x; acc[i][1] += a * bv.y;
                    acc[i][2] += a * bv.z; acc[i][3] += a * bv.w;
                }
            }
        }
        #pragma unroll
        for (int i = 0; i < 4; i++) {
            float4 r;
            r.x = fmaxf(acc[i][0], 0.f); r.y = fmaxf(acc[i][1], 0.f);
            r.z = fmaxf(acc[i][2], 0.f); r.w = fmaxf(acc[i][3], 0.f);
            *reinterpret_cast<float4*>(&Bs[(t0 + i) * E1 + e0 + te * 4]) = r;
        }
    }

    // ---------------- Phase 2: F = H @ W2 + b2 -> As ----------------
    for (int et = 0; et < 2; et++) {
        const int e0 = et * 128;
        float4 bini = *reinterpret_cast<const float4*>(&b2[e0 + te * 4]);
        float acc[4][4];
        #pragma unroll
        for (int i = 0; i < 4; i++) {
            acc[i][0] = bini.x; acc[i][1] = bini.y; acc[i][2] = bini.z; acc[i][3] = bini.w;
        }
        for (int k0 = 0; k0 < E1; k0 += KC) {
            __syncthreads();
            #pragma unroll
            for (int q = tid; q < KC * 32; q += NTHREADS) {
                int kk = q >> 5, c = q & 31;
                *reinterpret_cast<float4*>(&Wt[kk * WST + c * 4]) =
                    *reinterpret_cast<const float4*>(&W2[(k0 + kk) * DIM + e0 + c * 4]);
            }
            __syncthreads();
            #pragma unroll
            for (int kk = 0; kk < KC; kk++) {
                float4 bv = *reinterpret_cast<float4*>(&Wt[kk * WST + te * 4]);
                #pragma unroll
                for (int i = 0; i < 4; i++) {
                    float a = Bs[(t0 + i) * E1 + k0 + kk];
                    acc[i][0] += a * bv.x; acc[i][1] += a * bv.y;
                    acc[i][2] += a * bv.z; acc[i][3] += a * bv.w;
                }
            }
        }
        #pragma unroll
        for (int i = 0; i < 4; i++) {
            float4 r; r.x = acc[i][0]; r.y = acc[i][1]; r.z = acc[i][2]; r.w = acc[i][3];
            *reinterpret_cast<float4*>(&As[(t0 + i) * DIM + e0 + te * 4]) = r;
        }
    }
    __syncthreads();   // F complete everywhere; H now dead

    // ---------------- Phase 3a: stage memory patterns into Bs ----------------
    #pragma unroll
    for (int q = tid; q < NMEM * DIM / 4; q += NTHREADS) {
        int m = q >> 6, c = q & 63;
        *reinterpret_cast<float4*>(&Bs[m * DIM + c * 4]) =
            *reinterpret_cast<const float4*>(&Mem[m * DIM + c * 4]);
    }

    // ---------------- Phase 3b: LayerNorm (warp per 4 tokens) ----------------
    {
        float g8[8], be8[8];
        #pragma unroll
        for (int j = 0; j < 8; j++) { g8[j] = lng[lane + 32 * j]; be8[j] = lnb[lane + 32 * j]; }
        for (int ti = 0; ti < 4; ti++) {
            int t = t0 + ti;
            float x[8]; float s = 0.f, s2 = 0.f;
            #pragma unroll
            for (int j = 0; j < 8; j++) {
                x[j] = As[t * DIM + lane + 32 * j];
                s += x[j]; s2 += x[j] * x[j];
            }
            s = warp_sum(s); s2 = warp_sum(s2);
            float mean = s * (1.f / 256.f);
            float var  = s2 * (1.f / 256.f) - mean * mean;
            float rstd = rsqrtf(var + 1e-5f);
            float fs = 0.f;
            #pragma unroll
            for (int j = 0; j < 8; j++) {
                float v = (x[j] - mean) * rstd * g8[j] + be8[j];
                As[t * DIM + lane + 32 * j] = v;
                fs += v * v;
            }
            fs = warp_sum(fs);
            if (lane == 0) fsq[t] = fs;
        }
    }
    __syncthreads();

    // ---------------- Phase 3c: ||m||^2 per pattern ----------------
    for (int m = w; m < NMEM; m += 8) {
        float s = 0.f;
        #pragma unroll
        for (int j = 0; j < 8; j++) {
            float v = Bs[m * DIM + lane + 32 * j];
            s += v * v;
        }
        s = warp_sum(s);
        if (lane == 0) msq[m] = s;
    }
    __syncthreads();

    // ---------------- Phase 4: distances (warp per token) ----------------
    for (int ti = 0; ti < 4; ti++) {
        int t = t0 + ti;
        float f8[8];
        #pragma unroll
        for (int j = 0; j < 8; j++) f8[j] = As[t * DIM + lane + 32 * j];
        float fq = fsq[t];
        for (int m = 0; m < NMEM; m++) {
            float s = 0.f;
            #pragma unroll
            for (int j = 0; j < 8; j++) s += f8[j] * Bs[m * DIM + lane + 32 * j];
            s = warp_sum(s);
            if (lane == 0) {
                float d2 = fq + msq[m] - 2.f * s;
                dists[t * NMEM + m] = sqrtf(fmaxf(d2, 0.f));
            }
        }
    }
    __syncthreads();

    // ---------------- Phase 5: top-5 min -> sigmoid ----------------
    if (tid < TOK) {
        int t = tid;
        float acc = 0.f;
        #pragma unroll
        for (int k = 0; k < KNN; k++) {
            float best = FLT_MAX; int bi = 0;
            for (int m = 0; m < NMEM; m++) {
                float v = dists[t * NMEM + m];
                if (v < best) { best = v; bi = m; }
            }
            acc += best;
            dists[t * NMEM + bi] = FLT_MAX;
        }
        float avg = acc * (1.f / (float)KNN);
        int tg = tok0 + t;
        if (tg < ntok) out[tg] = 1.f / (1.f + expf(1.f - avg));
    }
}

extern "C" void kernel_launch(void* const* d_in, const int* in_sizes, int n_in,
                              void* d_out, int out_size) {
    const float* X   = (const float*)d_in[0];
    const float* Mem = (const float*)d_in[1];
    const float* W1  = (const float*)d_in[2];
    const float* b1  = (const float*)d_in[3];
    const float* W2  = (const float*)d_in[4];
    const float* b2  = (const float*)d_in[5];
    const float* g   = (const float*)d_in[6];
    const float* be  = (const float*)d_in[7];
    float* out = (float*)d_out;

    int ntok = out_size;                       // B*S tokens
    int grid = (ntok + TOK - 1) / TOK;

    cudaFuncSetAttribute(ipm_fused, cudaFuncAttributeMaxDynamicSharedMemorySize, SMEM_BYTES);
    ipm_fused<<<grid, NTHREADS, SMEM_BYTES>>>(X, Mem, W1, b1, W2, b2, g, be, out, ntok);
}

// round 3
// speedup vs baseline: 6.6788x; 6.6788x over previous
#include <cuda_runtime.h>
#include <cuda_bf16.h>
#include <math.h>
#include <float.h>
#include <stdint.h>

// ================= geometry =================
#define NTHR 256
#define MTOK 128

// smem byte map
#define XA_BASE   0          // X/feats bf16 image: 128 rows x 512B (64 KB)
#define H_BASE    65536      // H bf16 image: 128 rows x 1024B (128 KB); later dists
#define WB_BASE   196608     // 32 KB weight chunk buffer
#define SM_MEAN   229376     // 128 f32
#define SM_RSTD   229888     // 128 f32
#define SM_FSQ    230400     // 128 f32
#define SM_MSQ    230912     // 64 f32
#define SMEM_BYTES 231168

#define DIST_STRIDE 272      // bytes per dist row (68 floats) inside H region

// device scratch: pre-swizzled bf16 weight images (exact smem byte layout)
__device__ uint4 g_W1t[16384];   // 8 chunks x 32KB : [n64 rows x 512B]
__device__ uint4 g_W2t[16384];   // 8 chunks x 32KB : [n32 rows x 1024B]
__device__ uint4 g_Memt[2048];   // 1 tile 32KB     : [64 rows x 512B]
__device__ float g_msq[64];

// ================= asm helpers =================
__device__ __forceinline__ uint32_t smem_u32(const void* p) {
    uint32_t a;
    asm("{ .reg .u64 t; cvta.to.shared.u64 t, %1; cvt.u32.u64 %0, t; }" : "=r"(a) : "l"(p));
    return a;
}
#define LDSM4(r0, r1, r2, r3, a) \
    asm volatile("ldmatrix.sync.aligned.m8n8.x4.shared.b16 {%0,%1,%2,%3}, [%4];" \
        : "=r"(r0), "=r"(r1), "=r"(r2), "=r"(r3) : "r"(a))
#define STSM4(a, r0, r1, r2, r3) \
    asm volatile("stmatrix.sync.aligned.m8n8.x4.shared.b16 [%0], {%1,%2,%3,%4};" \
        :: "r"(a), "r"(r0), "r"(r1), "r"(r2), "r"(r3) : "memory")

__device__ __forceinline__ void mma16816(float* d, const uint32_t* a, const uint32_t* b) {
    asm volatile(
        "mma.sync.aligned.m16n8k16.row.col.f32.bf16.bf16.f32 "
        "{%0,%1,%2,%3}, {%4,%5,%6,%7}, {%8,%9}, {%0,%1,%2,%3};"
        : "+f"(d[0]), "+f"(d[1]), "+f"(d[2]), "+f"(d[3])
        : "r"(a[0]), "r"(a[1]), "r"(a[2]), "r"(a[3]), "r"(b[0]), "r"(b[1]));
}
__device__ __forceinline__ uint32_t packbf(float lo, float hi) {
    __nv_bfloat162 p = __floats2bfloat162_rn(lo, hi);
    return *reinterpret_cast<uint32_t*>(&p);
}

// ================= prep kernels =================
__global__ void prep_weights(const float* __restrict__ W1, const float* __restrict__ W2,
                             const float* __restrict__ Mem) {
    int e = blockIdx.x * 256 + threadIdx.x;
    if (e < 131072) {                               // W1t: [k=256][n=512] -> chunks of n64 x k256
        int n = e >> 8, k = e & 255;
        int c = n >> 6, np = n & 63;
        uint32_t off = (uint32_t)c * 32768u + np * 512u + (uint32_t)((((k >> 3) ^ (np & 7)) << 4) | ((k & 7) << 1));
        *((__nv_bfloat16*)((char*)g_W1t + off)) = __float2bfloat16(W1[k * 512 + n]);
    } else if (e < 262144) {                        // W2t: [k=512][n=256] -> chunks of n32 x k512
        int q = e - 131072;
        int n = q >> 9, k = q & 511;
        int c = n >> 5, np = n & 31;
        uint32_t off = (uint32_t)c * 32768u + np * 1024u + (uint32_t)((((k >> 3) ^ (np & 7)) << 4) | ((k & 7) << 1));
        *((__nv_bfloat16*)((char*)g_W2t + off)) = __float2bfloat16(W2[k * 256 + n]);
    } else if (e < 278528) {                        // Memt: 64 rows (50 real) x k256
        int q = e - 262144;
        int m = q >> 8, k = q & 255;
        float v = (m < 50) ? Mem[m * 256 + k] : 0.f;
        uint32_t off = (uint32_t)m * 512u + (uint32_t)((((k >> 3) ^ (m & 7)) << 4) | ((k & 7) << 1));
        *((__nv_bfloat16*)((char*)g_Memt + off)) = __float2bfloat16(v);
    }
}

__global__ void prep_msq(const float* __restrict__ Mem) {   // <<<64, 32>>>
    int m = blockIdx.x, lane = threadIdx.x;
    float s = 0.f;
    if (m < 50) {
        #pragma unroll
        for (int j = 0; j < 8; j++) {
            float v = Mem[m * 256 + lane + 32 * j];
            s += v * v;
        }
    }
    #pragma unroll
    for (int o = 16; o; o >>= 1) s += __shfl_xor_sync(0xffffffffu, s, o);
    if (lane == 0) g_msq[m] = s;
}

// ================= main fused kernel =================
__global__ __launch_bounds__(NTHR, 1)
void ipm_mma(const float* __restrict__ X,
             const float* __restrict__ b1, const float* __restrict__ b2,
             const float* __restrict__ lng, const float* __restrict__ lnb,
             float* __restrict__ out, int ntok)
{
    extern __shared__ __align__(1024) char smem[];
    const uint32_t sb = smem_u32(smem);
    const int tid  = threadIdx.x;
    const int lane = tid & 31;
    const int w    = tid >> 5;
    const int m0   = w * 16;
    const int tok0 = blockIdx.x * MTOK;

    float* sMean = reinterpret_cast<float*>(smem + SM_MEAN - 0) + 0;
    float* sRstd = reinterpret_cast<float*>(smem + SM_RSTD);
    float* sFsq  = reinterpret_cast<float*>(smem + SM_FSQ);
    float* sMsq  = reinterpret_cast<float*>(smem + SM_MSQ);
    sMean = reinterpret_cast<float*>(smem + SM_MEAN);

    // common lane-derived address pieces
    const uint32_t lrow16 = lane & 15;          // A/stm row-within-16
    const uint32_t asel   = lane >> 4;          // A/stm chunk offset
    const uint32_t sxr    = lane & 7;           // swizzle bits (row&7 == lane&7 everywhere we use it)
    const uint32_t bsel   = (lane >> 3) & 1;    // B chunk offset
    const uint32_t brow8  = (lane & 7) + ((lane >> 4) << 3);  // B row-within-16

    // -------- prologue: X -> bf16 swizzled; W1 chunk0 -> WB; msq --------
    {
        #pragma unroll
        for (int u = 0; u < 8; u++) {
            uint4 v = g_W1t[tid + 256 * u];
            *reinterpret_cast<uint4*>(smem + WB_BASE + (tid + 256 * u) * 16) = v;
        }
        if (tid < 64) sMsq[tid] = g_msq[tid];
        for (int q = tid; q < MTOK * 64; q += NTHR) {
            int r = q >> 6, k = (q & 63) * 4;
            int rg = tok0 + r; if (rg >= ntok) rg = ntok - 1;
            float4 v = *reinterpret_cast<const float4*>(&X[(long)rg * 256 + k]);
            uint2 pk; pk.x = packbf(v.x, v.y); pk.y = packbf(v.z, v.w);
            uint32_t off = r * 512 + ((((k >> 3) ^ (r & 7)) << 4) | ((k & 7) << 1));
            *reinterpret_cast<uint2*>(smem + XA_BASE + off) = pk;
        }
        __syncthreads();
    }

    const uint32_t aRow1 = sb + XA_BASE + (m0 + lrow16) * 512;   // X / feats (stride 512)
    const uint32_t aRow2 = sb + H_BASE + (m0 + lrow16) * 1024;   // H (stride 1024)

    // ================= GEMM1: H = relu(X @ W1 + b1) =================
    for (int c = 0; c < 8; c++) {
        uint4 pf[8];
        if (c < 7) {
            #pragma unroll
            for (int u = 0; u < 8; u++) pf[u] = g_W1t[(c + 1) * 2048 + tid + 256 * u];
        }
        // B row bases (4 n16-groups, stride 512)
        uint32_t bRow[4];
        #pragma unroll
        for (int g = 0; g < 4; g++) bRow[g] = sb + WB_BASE + (16 * g + brow8) * 512;

        float acc[8][4];
        #pragma unroll
        for (int j = 0; j < 8; j++) { acc[j][0] = acc[j][1] = acc[j][2] = acc[j][3] = 0.f; }

        #pragma unroll
        for (int kk = 0; kk < 16; kk++) {
            uint32_t a[4];
            LDSM4(a[0], a[1], a[2], a[3], aRow1 + (((2 * kk + asel) ^ sxr) << 4));
            uint32_t b[8][2];
            #pragma unroll
            for (int g = 0; g < 4; g++) {
                uint32_t r0, r1, r2, r3;
                LDSM4(r0, r1, r2, r3, bRow[g] + (((2 * kk + bsel) ^ sxr) << 4));
                b[2 * g][0] = r0; b[2 * g][1] = r1;
                b[2 * g + 1][0] = r2; b[2 * g + 1][1] = r3;
            }
            #pragma unroll
            for (int j = 0; j < 8; j++) mma16816(acc[j], a, b[j]);
        }

        // epilogue: +b1, relu, pack, stmatrix into H
        {
            const int n0 = c * 64;
            #pragma unroll
            for (int p = 0; p < 4; p++) {
                float2 bc0 = __ldg((const float2*)&b1[n0 + 16 * p + 2 * (lane & 3)]);
                float2 bc1 = __ldg((const float2*)&b1[n0 + 16 * p + 8 + 2 * (lane & 3)]);
                int j0 = 2 * p, j1 = 2 * p + 1;
                uint32_t q0 = packbf(fmaxf(acc[j0][0] + bc0.x, 0.f), fmaxf(acc[j0][1] + bc0.y, 0.f));
                uint32_t q1 = packbf(fmaxf(acc[j0][2] + bc0.x, 0.f), fmaxf(acc[j0][3] + bc0.y, 0.f));
                uint32_t q2 = packbf(fmaxf(acc[j1][0] + bc1.x, 0.f), fmaxf(acc[j1][1] + bc1.y, 0.f));
                uint32_t q3 = packbf(fmaxf(acc[j1][2] + bc1.x, 0.f), fmaxf(acc[j1][3] + bc1.y, 0.f));
                uint32_t jc = (n0 >> 3) + 2 * p;   // 16B-chunk index of n16 group
                uint32_t addr = aRow2 + (((jc + asel) ^ sxr) << 4);
                STSM4(addr, q0, q1, q2, q3);
            }
        }
        __syncthreads();
        if (c < 7) {
            #pragma unroll
            for (int u = 0; u < 8; u++)
                *reinterpret_cast<uint4*>(smem + WB_BASE + (tid + 256 * u) * 16) = pf[u];
        }
        __syncthreads();
    }

    // ================= GEMM2: F = H @ W2 + b2 (raw F -> feats; stats on the fly) =================
    float sA = 0.f, s2A = 0.f, sB = 0.f, s2B = 0.f;
    // first W2 chunk into WB
    {
        #pragma unroll
        for (int u = 0; u < 8; u++) {
            uint4 v = g_W2t[tid + 256 * u];
            *reinterpret_cast<uint4*>(smem + WB_BASE + (tid + 256 * u) * 16) = v;
        }
        __syncthreads();
    }
    for (int c = 0; c < 8; c++) {
        uint4 pf[8];
        {
            const uint4* src = (c < 7) ? (g_W2t + (c + 1) * 2048) : g_Memt;
            #pragma unroll
            for (int u = 0; u < 8; u++) pf[u] = src[tid + 256 * u];
        }
        uint32_t bRow[2];
        #pragma unroll
        for (int g = 0; g < 2; g++) bRow[g] = sb + WB_BASE + (16 * g + brow8) * 1024;

        float acc[4][4];
        #pragma unroll
        for (int j = 0; j < 4; j++) { acc[j][0] = acc[j][1] = acc[j][2] = acc[j][3] = 0.f; }

        #pragma unroll
        for (int kk = 0; kk < 32; kk++) {
            uint32_t a[4];
            LDSM4(a[0], a[1], a[2], a[3], aRow2 + (((2 * kk + asel) ^ sxr) << 4));
            uint32_t b[4][2];
            #pragma unroll
            for (int g = 0; g < 2; g++) {
                uint32_t r0, r1, r2, r3;
                LDSM4(r0, r1, r2, r3, bRow[g] + (((2 * kk + bsel) ^ sxr) << 4));
                b[2 * g][0] = r0; b[2 * g][1] = r1;
                b[2 * g + 1][0] = r2; b[2 * g + 1][1] = r3;
            }
            #pragma unroll
            for (int j = 0; j < 4; j++) mma16816(acc[j], a, b[j]);
        }

        // epilogue: +b2, stats, pack raw F -> feats (XA region)
        {
            const int n0 = c * 32;
            #pragma unroll
            for (int p = 0; p < 2; p++) {
                float2 bc0 = __ldg((const float2*)&b2[n0 + 16 * p + 2 * (lane & 3)]);
                float2 bc1 = __ldg((const float2*)&b2[n0 + 16 * p + 8 + 2 * (lane & 3)]);
                int j0 = 2 * p, j1 = 2 * p + 1;
                float vA0 = acc[j0][0] + bc0.x, vA1 = acc[j0][1] + bc0.y;
                float vB0 = acc[j0][2] + bc0.x, vB1 = acc[j0][3] + bc0.y;
                float vA2 = acc[j1][0] + bc1.x, vA3 = acc[j1][1] + bc1.y;
                float vB2 = acc[j1][2] + bc1.x, vB3 = acc[j1][3] + bc1.y;
                sA  += vA0 + vA1 + vA2 + vA3;
                s2A += vA0 * vA0 + vA1 * vA1 + vA2 * vA2 + vA3 * vA3;
                sB  += vB0 + vB1 + vB2 + vB3;
                s2B += vB0 * vB0 + vB1 * vB1 + vB2 * vB2 + vB3 * vB3;
                uint32_t q0 = packbf(vA0, vA1), q1 = packbf(vB0, vB1);
                uint32_t q2 = packbf(vA2, vA3), q3 = packbf(vB2, vB3);
                uint32_t jc = (n0 >> 3) + 2 * p;
                uint32_t addr = aRow1 + (((jc + asel) ^ sxr) << 4);
                STSM4(addr, q0, q1, q2, q3);
            }
        }
        __syncthreads();
        {
            #pragma unroll
            for (int u = 0; u < 8; u++)
                *reinterpret_cast<uint4*>(smem + WB_BASE + (tid + 256 * u) * 16) = pf[u];
        }
        __syncthreads();   // WB now holds next W2 chunk (or Mem tile after c==7)
    }

    // -------- finalize LN stats --------
    {
        sA  += __shfl_xor_sync(0xffffffffu, sA, 1);  sA  += __shfl_xor_sync(0xffffffffu, sA, 2);
        s2A += __shfl_xor_sync(0xffffffffu, s2A, 1); s2A += __shfl_xor_sync(0xffffffffu, s2A, 2);
        sB  += __shfl_xor_sync(0xffffffffu, sB, 1);  sB  += __shfl_xor_sync(0xffffffffu, sB, 2);
        s2B += __shfl_xor_sync(0xffffffffu, s2B, 1); s2B += __shfl_xor_sync(0xffffffffu, s2B, 2);
        if ((lane & 3) == 0) {
            int rA = m0 + (lane >> 2), rB = rA + 8;
            float mA = sA * (1.f / 256.f);
            float vA = s2A * (1.f / 256.f) - mA * mA;
            float mB = sB * (1.f / 256.f);
            float vB = s2B * (1.f / 256.f) - mB * mB;
            sMean[rA] = mA; sRstd[rA] = rsqrtf(vA + 1e-5f);
            sMean[rB] = mB; sRstd[rB] = rsqrtf(vB + 1e-5f);
        }
        __syncthreads();
    }

    // -------- normalization pass over feats (bf16 in XA) --------
    {
        int row = tid >> 1, half = tid & 1;
        float mean_r = sMean[row], rstd_r = sRstd[row];
        float fp = 0.f;
        int sxrow = row & 7;
        #pragma unroll
        for (int cc = 0; cc < 16; cc++) {
            int chunk = half * 16 + cc;
            char* p = smem + XA_BASE + row * 512 + ((chunk ^ sxrow) << 4);
            uint4 v = *reinterpret_cast<uint4*>(p);
            uint32_t* vp = reinterpret_cast<uint32_t*>(&v);
            int col0 = chunk * 8;
            float4 g0 = __ldg((const float4*)&lng[col0]);
            float4 g1 = __ldg((const float4*)&lng[col0 + 4]);
            float4 e0 = __ldg((const float4*)&lnb[col0]);
            float4 e1 = __ldg((const float4*)&lnb[col0 + 4]);
            float gg[8] = {g0.x, g0.y, g0.z, g0.w, g1.x, g1.y, g1.z, g1.w};
            float ee[8] = {e0.x, e0.y, e0.z, e0.w, e1.x, e1.y, e1.z, e1.w};
            #pragma unroll
            for (int q = 0; q < 4; q++) {
                __nv_bfloat162 pr = *reinterpret_cast<__nv_bfloat162*>(&vp[q]);
                float lo = __bfloat162float(pr.x), hi = __bfloat162float(pr.y);
                lo = (lo - mean_r) * rstd_r * gg[2 * q] + ee[2 * q];
                hi = (hi - mean_r) * rstd_r * gg[2 * q + 1] + ee[2 * q + 1];
                fp += lo * lo + hi * hi;
                vp[q] = packbf(lo, hi);
            }
            *reinterpret_cast<uint4*>(p) = v;
        }
        fp += __shfl_xor_sync(0xffffffffu, fp, 1);
        if (!half) sFsq[row] = fp;
        __syncthreads();
    }

    // ================= GEMM3: dots = feats @ Mem^T =================
    {
        uint32_t bRow[4];
        #pragma unroll
        for (int g = 0; g < 4; g++) bRow[g] = sb + WB_BASE + (16 * g + brow8) * 512;

        float acc[8][4];
        #pragma unroll
        for (int j = 0; j < 8; j++) { acc[j][0] = acc[j][1] = acc[j][2] = acc[j][3] = 0.f; }

        #pragma unroll
        for (int kk = 0; kk < 16; kk++) {
            uint32_t a[4];
            LDSM4(a[0], a[1], a[2], a[3], aRow1 + (((2 * kk + asel) ^ sxr) << 4));
            uint32_t b[8][2];
            #pragma unroll
            for (int g = 0; g < 4; g++) {
                uint32_t r0, r1, r2, r3;
                LDSM4(r0, r1, r2, r3, bRow[g] + (((2 * kk + bsel) ^ sxr) << 4));
                b[2 * g][0] = r0; b[2 * g][1] = r1;
                b[2 * g + 1][0] = r2; b[2 * g + 1][1] = r3;
            }
            #pragma unroll
            for (int j = 0; j < 8; j++) mma16816(acc[j], a, b[j]);
        }

        // distances -> smem (H region, stride 272B)
        int rA = m0 + (lane >> 2), rB = rA + 8;
        float fA = sFsq[rA], fB = sFsq[rB];
        #pragma unroll
        for (int j = 0; j < 8; j++) {
            int c0 = 8 * j + 2 * (lane & 3);
            float mq0 = sMsq[c0], mq1 = sMsq[c0 + 1];
            float2 dA, dB;
            dA.x = sqrtf(fmaxf(fA + mq0 - 2.f * acc[j][0], 0.f));
            dA.y = sqrtf(fmaxf(fA + mq1 - 2.f * acc[j][1], 0.f));
            dB.x = sqrtf(fmaxf(fB + mq0 - 2.f * acc[j][2], 0.f));
            dB.y = sqrtf(fmaxf(fB + mq1 - 2.f * acc[j][3], 0.f));
            *reinterpret_cast<float2*>(smem + H_BASE + rA * DIST_STRIDE + c0 * 4) = dA;
            *reinterpret_cast<float2*>(smem + H_BASE + rB * DIST_STRIDE + c0 * 4) = dB;
        }
        __syncthreads();
    }

    // ================= top-5 + sigmoid =================
    if (tid < MTOK) {
        const float* dr = reinterpret_cast<const float*>(smem + H_BASE + tid * DIST_STRIDE);
        float b0 = FLT_MAX, bq1 = FLT_MAX, bq2 = FLT_MAX, bq3 = FLT_MAX, bq4 = FLT_MAX;
        #pragma unroll
        for (int m = 0; m < 50; m++) {
            float v = dr[m];
            if (v < bq4) {
                bq4 = v;
                if (bq4 < bq3) { float x = bq3; bq3 = bq4; bq4 = x; }
                if (bq3 < bq2) { float x = bq2; bq2 = bq3; bq3 = x; }
                if (bq2 < bq1) { float x = bq1; bq1 = bq2; bq2 = x; }
                if (bq1 < b0)  { float x = b0;  b0  = bq1; bq1 = x; }
            }
        }
        float avg = (b0 + bq1 + bq2 + bq3 + bq4) * 0.2f;
        int tg = tok0 + tid;
        if (tg < ntok) out[tg] = 1.f / (1.f + expf(1.f - avg));
    }
}

// ================= launch =================
extern "C" void kernel_launch(void* const* d_in, const int* in_sizes, int n_in,
                              void* d_out, int out_size) {
    const float* X   = (const float*)d_in[0];
    const float* Mem = (const float*)d_in[1];
    const float* W1  = (const float*)d_in[2];
    const float* b1  = (const float*)d_in[3];
    const float* W2  = (const float*)d_in[4];
    const float* b2  = (const float*)d_in[5];
    const float* g   = (const float*)d_in[6];
    const float* be  = (const float*)d_in[7];
    float* out = (float*)d_out;

    int ntok = out_size;
    int grid = (ntok + MTOK - 1) / MTOK;

    prep_weights<<<1088, 256>>>(W1, W2, Mem);
    prep_msq<<<64, 32>>>(Mem);

    cudaFuncSetAttribute(ipm_mma, cudaFuncAttributeMaxDynamicSharedMemorySize, SMEM_BYTES);
    ipm_mma<<<grid, NTHR, SMEM_BYTES>>>(X, b1, b2, g, be, out, ntok);
}

// round 4
// speedup vs baseline: 7.6995x; 1.1528x over previous
#include <cuda_runtime.h>
#include <cuda_bf16.h>
#include <math.h>
#include <float.h>
#include <stdint.h>

// ================= geometry =================
#define NTHR 256
#define MTOK 128

// smem byte map
#define XA_BASE   0          // X/feats bf16 image: 128 rows x 512B (64 KB)
#define H_BASE    65536      // H bf16 image: 128 rows x 1024B (128 KB); later dists
#define WB_BASE   196608     // 32 KB weight chunk buffer
#define SM_MEAN   229376     // 128 f32
#define SM_RSTD   229888     // 128 f32
#define SM_FSQ    230400     // 128 f32
#define SM_MSQ    230912     // 64 f32
#define SMEM_BYTES 231168

#define DIST_STRIDE 272      // bytes per dist row (68 floats) inside H region

// device scratch: pre-swizzled bf16 weight images (exact smem byte layout)
__device__ uint4 g_W1t[16384];   // 8 chunks x 32KB : [n64 rows x 512B(k256)]
__device__ uint4 g_W2t[16384];   // 8 chunks x 32KB : [(nc,kh) -> n64 rows x 512B(k256)]
__device__ uint4 g_Memt[2048];   // 1 tile 32KB     : [64 rows x 512B(k256)]
__device__ float g_msq[64];

// ================= asm helpers =================
__device__ __forceinline__ uint32_t smem_u32(const void* p) {
    uint32_t a;
    asm("{ .reg .u64 t; cvta.to.shared.u64 t, %1; cvt.u32.u64 %0, t; }" : "=r"(a) : "l"(p));
    return a;
}
#define LDSM4(r0, r1, r2, r3, a) \
    asm volatile("ldmatrix.sync.aligned.m8n8.x4.shared.b16 {%0,%1,%2,%3}, [%4];" \
        : "=r"(r0), "=r"(r1), "=r"(r2), "=r"(r3) : "r"(a))
#define STSM4(a, r0, r1, r2, r3) \
    asm volatile("stmatrix.sync.aligned.m8n8.x4.shared.b16 [%0], {%1,%2,%3,%4};" \
        :: "r"(a), "r"(r0), "r"(r1), "r"(r2), "r"(r3) : "memory")

__device__ __forceinline__ void mma16816(float* d, const uint32_t* a, const uint32_t* b) {
    asm volatile(
        "mma.sync.aligned.m16n8k16.row.col.f32.bf16.bf16.f32 "
        "{%0,%1,%2,%3}, {%4,%5,%6,%7}, {%8,%9}, {%0,%1,%2,%3};"
        : "+f"(d[0]), "+f"(d[1]), "+f"(d[2]), "+f"(d[3])
        : "r"(a[0]), "r"(a[1]), "r"(a[2]), "r"(a[3]), "r"(b[0]), "r"(b[1]));
}
__device__ __forceinline__ uint32_t packbf(float lo, float hi) {
    __nv_bfloat162 p = __floats2bfloat162_rn(lo, hi);
    return *reinterpret_cast<uint32_t*>(&p);
}

// ================= prep kernels =================
__global__ void prep_weights(const float* __restrict__ W1, const float* __restrict__ W2,
                             const float* __restrict__ Mem) {
    int e = blockIdx.x * 256 + threadIdx.x;
    if (e < 131072) {                               // W1t: [k=256][n=512] -> 8 chunks n64 x k256
        int n = e >> 8, k = e & 255;
        int c = n >> 6, np = n & 63;
        uint32_t off = (uint32_t)c * 32768u + np * 512u + (uint32_t)((((k >> 3) ^ (np & 7)) << 4) | ((k & 7) << 1));
        *((__nv_bfloat16*)((char*)g_W1t + off)) = __float2bfloat16(W1[k * 512 + n]);
    } else if (e < 262144) {                        // W2t: [k=512][n=256] -> chunks (nc*2+kh): n64 x k256
        int q = e - 131072;
        int n = q >> 9, k = q & 511;
        int c2 = (n >> 6) * 2 + (k >> 8);
        int np = n & 63, kl = k & 255;
        uint32_t off = (uint32_t)c2 * 32768u + np * 512u + (uint32_t)((((kl >> 3) ^ (np & 7)) << 4) | ((kl & 7) << 1));
        *((__nv_bfloat16*)((char*)g_W2t + off)) = __float2bfloat16(W2[k * 256 + n]);
    } else if (e < 278528) {                        // Memt: 64 rows (50 real) x k256
        int q = e - 262144;
        int m = q >> 8, k = q & 255;
        float v = (m < 50) ? Mem[m * 256 + k] : 0.f;
        uint32_t off = (uint32_t)m * 512u + (uint32_t)((((k >> 3) ^ (m & 7)) << 4) | ((k & 7) << 1));
        *((__nv_bfloat16*)((char*)g_Memt + off)) = __float2bfloat16(v);
    }
}

__global__ void prep_msq(const float* __restrict__ Mem) {   // <<<64, 32>>>
    int m = blockIdx.x, lane = threadIdx.x;
    float s = 0.f;
    if (m < 50) {
        #pragma unroll
        for (int j = 0; j < 8; j++) {
            float v = Mem[m * 256 + lane + 32 * j];
            s += v * v;
        }
    }
    #pragma unroll
    for (int o = 16; o; o >>= 1) s += __shfl_xor_sync(0xffffffffu, s, o);
    if (lane == 0) g_msq[m] = s;
}

// ================= main fused kernel =================
__global__ __launch_bounds__(NTHR, 1)
void ipm_mma(const float* __restrict__ X,
             const float* __restrict__ b1, const float* __restrict__ b2,
             const float* __restrict__ lng, const float* __restrict__ lnb,
             float* __restrict__ out, int ntok)
{
    extern __shared__ __align__(1024) char smem[];
    const uint32_t sb = smem_u32(smem);
    const int tid  = threadIdx.x;
    const int lane = tid & 31;
    const int w    = tid >> 5;
    const int mw   = w & 3;            // M group (32 rows)
    const int nw   = w >> 2;           // N half
    const int tok0 = blockIdx.x * MTOK;

    float* sMean = reinterpret_cast<float*>(smem + SM_MEAN);
    float* sRstd = reinterpret_cast<float*>(smem + SM_RSTD);
    float* sFsq  = reinterpret_cast<float*>(smem + SM_FSQ);
    float* sMsq  = reinterpret_cast<float*>(smem + SM_MSQ);

    const uint32_t lrow16 = lane & 15;
    const uint32_t asel   = lane >> 4;
    const uint32_t sxr    = lane & 7;
    const uint32_t bsel   = (lane >> 3) & 1;
    const uint32_t brow8  = (lane & 7) + ((lane >> 4) << 3);

    // -------- prologue: W1 chunk0 -> WB; msq; X -> bf16 swizzled --------
    {
        #pragma unroll
        for (int u = 0; u < 8; u++) {
            uint4 v = g_W1t[tid + 256 * u];
            *reinterpret_cast<uint4*>(smem + WB_BASE + (tid + 256 * u) * 16) = v;
        }
        if (tid < 64) sMsq[tid] = g_msq[tid];
        for (int q = tid; q < MTOK * 64; q += NTHR) {
            int r = q >> 6, k = (q & 63) * 4;
            int rg = tok0 + r; if (rg >= ntok) rg = ntok - 1;
            float4 v = *reinterpret_cast<const float4*>(&X[(long)rg * 256 + k]);
            uint2 pk; pk.x = packbf(v.x, v.y); pk.y = packbf(v.z, v.w);
            uint32_t off = r * 512 + ((((k >> 3) ^ (r & 7)) << 4) | ((k & 7) << 1));
            *reinterpret_cast<uint2*>(smem + XA_BASE + off) = pk;
        }
        __syncthreads();
    }

    // A-row bases: two m16 tiles per warp
    uint32_t aX[2], aH[2];
    #pragma unroll
    for (int t = 0; t < 2; t++) {
        aX[t] = sb + XA_BASE + (mw * 32 + 16 * t + lrow16) * 512;    // X / feats
        aH[t] = sb + H_BASE  + (mw * 32 + 16 * t + lrow16) * 1024;   // H
    }
    // B-row bases within WB (warp's n32: two n16 groups)
    uint32_t bW[2];
    #pragma unroll
    for (int g = 0; g < 2; g++) bW[g] = sb + WB_BASE + (nw * 32 + 16 * g + brow8) * 512;

    // ================= GEMM1: H = relu(X @ W1 + b1), 8 chunks n64 x k256 =================
    for (int c = 0; c < 8; c++) {
        uint4 pf[8];
        {
            const uint4* src = (c < 7) ? (g_W1t + (c + 1) * 2048) : g_W2t;
            #pragma unroll
            for (int u = 0; u < 8; u++) pf[u] = src[tid + 256 * u];
        }
        float acc[2][4][4];
        #pragma unroll
        for (int t = 0; t < 2; t++)
            #pragma unroll
            for (int j = 0; j < 4; j++)
                acc[t][j][0] = acc[t][j][1] = acc[t][j][2] = acc[t][j][3] = 0.f;

        #pragma unroll
        for (int kk = 0; kk < 16; kk++) {
            uint32_t a[2][4], b[4][2];
            uint32_t ksw = ((2 * kk + asel) ^ sxr) << 4;
            uint32_t ksb = ((2 * kk + bsel) ^ sxr) << 4;
            #pragma unroll
            for (int t = 0; t < 2; t++) LDSM4(a[t][0], a[t][1], a[t][2], a[t][3], aX[t] + ksw);
            #pragma unroll
            for (int g = 0; g < 2; g++) {
                uint32_t r0, r1, r2, r3;
                LDSM4(r0, r1, r2, r3, bW[g] + ksb);
                b[2 * g][0] = r0; b[2 * g][1] = r1;
                b[2 * g + 1][0] = r2; b[2 * g + 1][1] = r3;
            }
            #pragma unroll
            for (int t = 0; t < 2; t++)
                #pragma unroll
                for (int j = 0; j < 4; j++) mma16816(acc[t][j], a[t], b[j]);
        }

        // epilogue: +b1, relu, pack, stmatrix into H
        {
            const int n0 = c * 64 + nw * 32;
            #pragma unroll
            for (int g = 0; g < 2; g++) {
                float2 bc0 = __ldg((const float2*)&b1[n0 + 16 * g + 2 * (lane & 3)]);
                float2 bc1 = __ldg((const float2*)&b1[n0 + 16 * g + 8 + 2 * (lane & 3)]);
                #pragma unroll
                for (int t = 0; t < 2; t++) {
                    int j0 = 2 * g, j1 = 2 * g + 1;
                    uint32_t q0 = packbf(fmaxf(acc[t][j0][0] + bc0.x, 0.f), fmaxf(acc[t][j0][1] + bc0.y, 0.f));
                    uint32_t q1 = packbf(fmaxf(acc[t][j0][2] + bc0.x, 0.f), fmaxf(acc[t][j0][3] + bc0.y, 0.f));
                    uint32_t q2 = packbf(fmaxf(acc[t][j1][0] + bc1.x, 0.f), fmaxf(acc[t][j1][1] + bc1.y, 0.f));
                    uint32_t q3 = packbf(fmaxf(acc[t][j1][2] + bc1.x, 0.f), fmaxf(acc[t][j1][3] + bc1.y, 0.f));
                    uint32_t jc = (uint32_t)(c * 8 + nw * 4 + 2 * g);
                    STSM4(aH[t] + (((jc + asel) ^ sxr) << 4), q0, q1, q2, q3);
                }
            }
        }
        __syncthreads();
        #pragma unroll
        for (int u = 0; u < 8; u++)
            *reinterpret_cast<uint4*>(smem + WB_BASE + (tid + 256 * u) * 16) = pf[u];
        __syncthreads();
    }

    // ================= GEMM2: F = H @ W2 + b2, chunks (nc x kh) n64 x k256 =================
    float st[2][2], st2[2][2];
    #pragma unroll
    for (int t = 0; t < 2; t++) { st[t][0] = st[t][1] = st2[t][0] = st2[t][1] = 0.f; }

    for (int nc = 0; nc < 4; nc++) {
        float acc[2][4][4];
        #pragma unroll
        for (int t = 0; t < 2; t++)
            #pragma unroll
            for (int j = 0; j < 4; j++)
                acc[t][j][0] = acc[t][j][1] = acc[t][j][2] = acc[t][j][3] = 0.f;

        for (int kh = 0; kh < 2; kh++) {
            const int ci = nc * 2 + kh;     // 0..7
            uint4 pf[8];
            {
                const uint4* src = (ci < 7) ? (g_W2t + (ci + 1) * 2048) : g_Memt;
                #pragma unroll
                for (int u = 0; u < 8; u++) pf[u] = src[tid + 256 * u];
            }
            #pragma unroll
            for (int kk = 0; kk < 16; kk++) {
                uint32_t a[2][4], b[4][2];
                uint32_t ksw = ((kh * 32 + 2 * kk + asel) ^ sxr) << 4;
                uint32_t ksb = ((2 * kk + bsel) ^ sxr) << 4;
                #pragma unroll
                for (int t = 0; t < 2; t++) LDSM4(a[t][0], a[t][1], a[t][2], a[t][3], aH[t] + ksw);
                #pragma unroll
                for (int g = 0; g < 2; g++) {
                    uint32_t r0, r1, r2, r3;
                    LDSM4(r0, r1, r2, r3, bW[g] + ksb);
                    b[2 * g][0] = r0; b[2 * g][1] = r1;
                    b[2 * g + 1][0] = r2; b[2 * g + 1][1] = r3;
                }
                #pragma unroll
                for (int t = 0; t < 2; t++)
                    #pragma unroll
                    for (int j = 0; j < 4; j++) mma16816(acc[t][j], a[t], b[j]);
            }

            // epilogue only after second k-half
            if (kh == 1) {
                const int n0 = nc * 64 + nw * 32;
                #pragma unroll
                for (int g = 0; g < 2; g++) {
                    float2 bc0 = __ldg((const float2*)&b2[n0 + 16 * g + 2 * (lane & 3)]);
                    float2 bc1 = __ldg((const float2*)&b2[n0 + 16 * g + 8 + 2 * (lane & 3)]);
                    #pragma unroll
                    for (int t = 0; t < 2; t++) {
                        int j0 = 2 * g, j1 = 2 * g + 1;
                        float vA0 = acc[t][j0][0] + bc0.x, vA1 = acc[t][j0][1] + bc0.y;
                        float vB0 = acc[t][j0][2] + bc0.x, vB1 = acc[t][j0][3] + bc0.y;
                        float vA2 = acc[t][j1][0] + bc1.x, vA3 = acc[t][j1][1] + bc1.y;
                        float vB2 = acc[t][j1][2] + bc1.x, vB3 = acc[t][j1][3] + bc1.y;
                        st[t][0]  += vA0 + vA1 + vA2 + vA3;
                        st2[t][0] += vA0 * vA0 + vA1 * vA1 + vA2 * vA2 + vA3 * vA3;
                        st[t][1]  += vB0 + vB1 + vB2 + vB3;
                        st2[t][1] += vB0 * vB0 + vB1 * vB1 + vB2 * vB2 + vB3 * vB3;
                        uint32_t q0 = packbf(vA0, vA1), q1 = packbf(vB0, vB1);
                        uint32_t q2 = packbf(vA2, vA3), q3 = packbf(vB2, vB3);
                        uint32_t jc = (uint32_t)(nc * 8 + nw * 4 + 2 * g);
                        STSM4(aX[t] + (((jc + asel) ^ sxr) << 4), q0, q1, q2, q3);
                    }
                }
            }
            __syncthreads();
            #pragma unroll
            for (int u = 0; u < 8; u++)
                *reinterpret_cast<uint4*>(smem + WB_BASE + (tid + 256 * u) * 16) = pf[u];
            __syncthreads();   // after ci==7 this leaves Memt in WB
        }
    }

    // -------- finalize LN stats (4 rows per thread quad) --------
    {
        #pragma unroll
        for (int t = 0; t < 2; t++)
            #pragma unroll
            for (int h = 0; h < 2; h++) {
                float s = st[t][h], s2 = st2[t][h];
                s  += __shfl_xor_sync(0xffffffffu, s, 1);  s  += __shfl_xor_sync(0xffffffffu, s, 2);
                s2 += __shfl_xor_sync(0xffffffffu, s2, 1); s2 += __shfl_xor_sync(0xffffffffu, s2, 2);
                if ((lane & 3) == 0) {
                    int r = mw * 32 + 16 * t + 8 * h + (lane >> 2);
                    float m = s * (1.f / 256.f);
                    float v = s2 * (1.f / 256.f) - m * m;
                    sMean[r] = m; sRstd[r] = rsqrtf(v + 1e-5f);
                }
            }
        __syncthreads();
    }

    // -------- normalization pass over feats (bf16 in XA) --------
    {
        int row = tid >> 1, half = tid & 1;
        float mean_r = sMean[row], rstd_r = sRstd[row];
        float fp = 0.f;
        int sxrow = row & 7;
        #pragma unroll
        for (int cc = 0; cc < 16; cc++) {
            int chunk = half * 16 + cc;
            char* p = smem + XA_BASE + row * 512 + ((chunk ^ sxrow) << 4);
            uint4 v = *reinterpret_cast<uint4*>(p);
            uint32_t* vp = reinterpret_cast<uint32_t*>(&v);
            int col0 = chunk * 8;
            float4 g0 = __ldg((const float4*)&lng[col0]);
            float4 g1 = __ldg((const float4*)&lng[col0 + 4]);
            float4 e0 = __ldg((const float4*)&lnb[col0]);
            float4 e1 = __ldg((const float4*)&lnb[col0 + 4]);
            float gg[8] = {g0.x, g0.y, g0.z, g0.w, g1.x, g1.y, g1.z, g1.w};
            float ee[8] = {e0.x, e0.y, e0.z, e0.w, e1.x, e1.y, e1.z, e1.w};
            #pragma unroll
            for (int q = 0; q < 4; q++) {
                __nv_bfloat162 pr = *reinterpret_cast<__nv_bfloat162*>(&vp[q]);
                float lo = __bfloat162float(pr.x), hi = __bfloat162float(pr.y);
                lo = (lo - mean_r) * rstd_r * gg[2 * q] + ee[2 * q];
                hi = (hi - mean_r) * rstd_r * gg[2 * q + 1] + ee[2 * q + 1];
                fp += lo * lo + hi * hi;
                vp[q] = packbf(lo, hi);
            }
            *reinterpret_cast<uint4*>(p) = v;
        }
        fp += __shfl_xor_sync(0xffffffffu, fp, 1);
        if (!half) sFsq[row] = fp;
        __syncthreads();
    }

    // ================= GEMM3: dots = feats @ Mem^T (Memt already in WB) =================
    {
        float acc[2][4][4];
        #pragma unroll
        for (int t = 0; t < 2; t++)
            #pragma unroll
            for (int j = 0; j < 4; j++)
                acc[t][j][0] = acc[t][j][1] = acc[t][j][2] = acc[t][j][3] = 0.f;

        #pragma unroll
        for (int kk = 0; kk < 16; kk++) {
            uint32_t a[2][4], b[4][2];
            uint32_t ksw = ((2 * kk + asel) ^ sxr) << 4;
            uint32_t ksb = ((2 * kk + bsel) ^ sxr) << 4;
            #pragma unroll
            for (int t = 0; t < 2; t++) LDSM4(a[t][0], a[t][1], a[t][2], a[t][3], aX[t] + ksw);
            #pragma unroll
            for (int g = 0; g < 2; g++) {
                uint32_t r0, r1, r2, r3;
                LDSM4(r0, r1, r2, r3, bW[g] + ksb);
                b[2 * g][0] = r0; b[2 * g][1] = r1;
                b[2 * g + 1][0] = r2; b[2 * g + 1][1] = r3;
            }
            #pragma unroll
            for (int t = 0; t < 2; t++)
                #pragma unroll
                for (int j = 0; j < 4; j++) mma16816(acc[t][j], a[t], b[j]);
        }

        // distances -> smem (H region, stride 272B)
        #pragma unroll
        for (int t = 0; t < 2; t++) {
            int rA = mw * 32 + 16 * t + (lane >> 2), rB = rA + 8;
            float fA = sFsq[rA], fB = sFsq[rB];
            #pragma unroll
            for (int j = 0; j < 4; j++) {
                int g = j >> 1, u = j & 1;
                int c0 = nw * 32 + 16 * g + 8 * u + 2 * (lane & 3);
                float mq0 = sMsq[c0], mq1 = sMsq[c0 + 1];
                float2 dA, dB;
                dA.x = sqrtf(fmaxf(fA + mq0 - 2.f * acc[t][j][0], 0.f));
                dA.y = sqrtf(fmaxf(fA + mq1 - 2.f * acc[t][j][1], 0.f));
                dB.x = sqrtf(fmaxf(fB + mq0 - 2.f * acc[t][j][2], 0.f));
                dB.y = sqrtf(fmaxf(fB + mq1 - 2.f * acc[t][j][3], 0.f));
                *reinterpret_cast<float2*>(smem + H_BASE + rA * DIST_STRIDE + c0 * 4) = dA;
                *reinterpret_cast<float2*>(smem + H_BASE + rB * DIST_STRIDE + c0 * 4) = dB;
            }
        }
        __syncthreads();
    }

    // ================= top-5 + sigmoid =================
    if (tid < MTOK) {
        const float* dr = reinterpret_cast<const float*>(smem + H_BASE + tid * DIST_STRIDE);
        float b0 = FLT_MAX, bq1 = FLT_MAX, bq2 = FLT_MAX, bq3 = FLT_MAX, bq4 = FLT_MAX;
        #pragma unroll
        for (int m = 0; m < 50; m++) {
            float v = dr[m];
            if (v < bq4) {
                bq4 = v;
                if (bq4 < bq3) { float x = bq3; bq3 = bq4; bq4 = x; }
                if (bq3 < bq2) { float x = bq2; bq2 = bq3; bq3 = x; }
                if (bq2 < bq1) { float x = bq1; bq1 = bq2; bq2 = x; }
                if (bq1 < b0)  { float x = b0;  b0  = bq1; bq1 = x; }
            }
        }
        float avg = (b0 + bq1 + bq2 + bq3 + bq4) * 0.2f;
        int tg = tok0 + tid;
        if (tg < ntok) out[tg] = 1.f / (1.f + expf(1.f - avg));
    }
}

// ================= launch =================
extern "C" void kernel_launch(void* const* d_in, const int* in_sizes, int n_in,
                              void* d_out, int out_size) {
    const float* X   = (const float*)d_in[0];
    const float* Mem = (const float*)d_in[1];
    const float* W1  = (const float*)d_in[2];
    const float* b1  = (const float*)d_in[3];
    const float* W2  = (const float*)d_in[4];
    const float* b2  = (const float*)d_in[5];
    const float* g   = (const float*)d_in[6];
    const float* be  = (const float*)d_in[7];
    float* out = (float*)d_out;

    int ntok = out_size;
    int grid = (ntok + MTOK - 1) / MTOK;

    prep_weights<<<1088, 256>>>(W1, W2, Mem);
    prep_msq<<<64, 32>>>(Mem);

    cudaFuncSetAttribute(ipm_mma, cudaFuncAttributeMaxDynamicSharedMemorySize, SMEM_BYTES);
    ipm_mma<<<grid, NTHR, SMEM_BYTES>>>(X, b1, b2, g, be, out, ntok);
}

// round 5
// speedup vs baseline: 8.5604x; 1.1118x over previous
#include <cuda_runtime.h>
#include <cuda_bf16.h>
#include <math.h>
#include <float.h>
#include <stdint.h>

// ================= geometry =================
#define NTHR 256
#define MTOK 128

// smem byte map
#define XA_BASE   0          // X/feats bf16 image: 128 rows x 512B (64 KB)
#define H_BASE    65536      // H bf16 image: 128 rows x 1024B (128 KB); later dists
#define WB_BASE   196608     // 2 x 16 KB weight chunk buffers
#define SM_MEAN   229376     // 128 f32
#define SM_RSTD   229888     // 128 f32
#define SM_FSQ    230400     // 128 f32
#define SM_MSQ    230912     // 64 f32
#define SMEM_BYTES 231168

#define DIST_STRIDE 272      // bytes per dist row inside H region

// device scratch: pre-swizzled bf16 weight images, 16KB chunks n64 x k128
__device__ uint4 g_W1t[16384];   // 16 chunks: (nb*2+kc)
__device__ uint4 g_W2t[16384];   // 16 chunks: (nc*4+kc)
__device__ uint4 g_Memt[2048];   // 2 chunks: kc
__device__ float g_msq[64];

// ================= asm helpers =================
__device__ __forceinline__ uint32_t smem_u32(const void* p) {
    uint32_t a;
    asm("{ .reg .u64 t; cvta.to.shared.u64 t, %1; cvt.u32.u64 %0, t; }" : "=r"(a) : "l"(p));
    return a;
}
#define LDSM4(r0, r1, r2, r3, a) \
    asm volatile("ldmatrix.sync.aligned.m8n8.x4.shared.b16 {%0,%1,%2,%3}, [%4];" \
        : "=r"(r0), "=r"(r1), "=r"(r2), "=r"(r3) : "r"(a))
#define STSM4(a, r0, r1, r2, r3) \
    asm volatile("stmatrix.sync.aligned.m8n8.x4.shared.b16 [%0], {%1,%2,%3,%4};" \
        :: "r"(a), "r"(r0), "r"(r1), "r"(r2), "r"(r3) : "memory")
#define CP16(dst, src) \
    asm volatile("cp.async.cg.shared.global [%0], [%1], 16;" :: "r"(dst), "l"(src))
#define CP_COMMIT() asm volatile("cp.async.commit_group;" ::: "memory")
#define CP_WAIT0()  asm volatile("cp.async.wait_group 0;" ::: "memory")
#define CP_WAIT1()  asm volatile("cp.async.wait_group 1;" ::: "memory")

__device__ __forceinline__ void mma16816(float* d, const uint32_t* a, const uint32_t* b) {
    asm volatile(
        "mma.sync.aligned.m16n8k16.row.col.f32.bf16.bf16.f32 "
        "{%0,%1,%2,%3}, {%4,%5,%6,%7}, {%8,%9}, {%0,%1,%2,%3};"
        : "+f"(d[0]), "+f"(d[1]), "+f"(d[2]), "+f"(d[3])
        : "r"(a[0]), "r"(a[1]), "r"(a[2]), "r"(a[3]), "r"(b[0]), "r"(b[1]));
}
__device__ __forceinline__ uint32_t packbf(float lo, float hi) {
    __nv_bfloat162 p = __floats2bfloat162_rn(lo, hi);
    return *reinterpret_cast<uint32_t*>(&p);
}

// ================= prep kernels =================
__global__ void prep_weights(const float* __restrict__ W1, const float* __restrict__ W2,
                             const float* __restrict__ Mem) {
    int e = blockIdx.x * 256 + threadIdx.x;
    if (e < 131072) {                               // W1t: [k=256][n=512]
        int n = e >> 8, k = e & 255;
        int nb = n >> 6, np = n & 63, kc = k >> 7, kl = k & 127;
        uint32_t off = (uint32_t)(nb * 2 + kc) * 16384u + np * 256u
                     + (uint32_t)((((kl >> 3) ^ (np & 7)) << 4) | ((kl & 7) << 1));
        *((__nv_bfloat16*)((char*)g_W1t + off)) = __float2bfloat16(W1[k * 512 + n]);
    } else if (e < 262144) {                        // W2t: [k=512][n=256]
        int q = e - 131072;
        int n = q >> 9, k = q & 511;
        int nc = n >> 6, np = n & 63, kc = k >> 7, kl = k & 127;
        uint32_t off = (uint32_t)(nc * 4 + kc) * 16384u + np * 256u
                     + (uint32_t)((((kl >> 3) ^ (np & 7)) << 4) | ((kl & 7) << 1));
        *((__nv_bfloat16*)((char*)g_W2t + off)) = __float2bfloat16(W2[k * 256 + n]);
    } else if (e < 278528) {                        // Memt: 64 rows (50 real) x k256
        int q = e - 262144;
        int m = q >> 8, k = q & 255;
        float v = (m < 50) ? Mem[m * 256 + k] : 0.f;
        int kc = k >> 7, kl = k & 127;
        uint32_t off = (uint32_t)kc * 16384u + m * 256u
                     + (uint32_t)((((kl >> 3) ^ (m & 7)) << 4) | ((kl & 7) << 1));
        *((__nv_bfloat16*)((char*)g_Memt + off)) = __float2bfloat16(v);
    }
}

__global__ void prep_msq(const float* __restrict__ Mem) {   // <<<64, 32>>>
    int m = blockIdx.x, lane = threadIdx.x;
    float s = 0.f;
    if (m < 50) {
        #pragma unroll
        for (int j = 0; j < 8; j++) {
            float v = Mem[m * 256 + lane + 32 * j];
            s += v * v;
        }
    }
    #pragma unroll
    for (int o = 16; o; o >>= 1) s += __shfl_xor_sync(0xffffffffu, s, o);
    if (lane == 0) g_msq[m] = s;
}

// chunk source pointer: 0..15 W1, 16..31 W2, 32..33 Mem
__device__ __forceinline__ const uint4* chunk_src(int q) {
    return (q < 16) ? (g_W1t + q * 1024)
         : (q < 32) ? (g_W2t + (q - 16) * 1024)
                    : (g_Memt + (q - 32) * 1024);
}

// ================= main fused kernel =================
__global__ __launch_bounds__(NTHR, 1)
void ipm_mma(const float* __restrict__ X,
             const float* __restrict__ b1, const float* __restrict__ b2,
             const float* __restrict__ lng, const float* __restrict__ lnb,
             float* __restrict__ out, int ntok)
{
    extern __shared__ __align__(1024) char smem[];
    const uint32_t sb = smem_u32(smem);
    const int tid  = threadIdx.x;
    const int lane = tid & 31;
    const int w    = tid >> 5;
    const int mw   = w & 3;            // M group (32 rows)
    const int nw   = w >> 2;           // N half
    const int tok0 = blockIdx.x * MTOK;

    float* sMean = reinterpret_cast<float*>(smem + SM_MEAN);
    float* sRstd = reinterpret_cast<float*>(smem + SM_RSTD);
    float* sFsq  = reinterpret_cast<float*>(smem + SM_FSQ);
    float* sMsq  = reinterpret_cast<float*>(smem + SM_MSQ);

    const uint32_t lrow16 = lane & 15;
    const uint32_t asel   = lane >> 4;
    const uint32_t sxr    = lane & 7;
    const uint32_t bsel   = (lane >> 3) & 1;
    const uint32_t brow8  = (lane & 7) + ((lane >> 4) << 3);

    const uint32_t cpdst = sb + WB_BASE + tid * 16;

    // issue async load of chunk q into buffer b
    auto issue = [&](int q, int b) {
        const uint4* src = chunk_src(q) + tid;
        uint32_t d = cpdst + (uint32_t)b * 16384u;
        #pragma unroll
        for (int u = 0; u < 4; u++) CP16(d + u * 4096u, src + u * 256);
        CP_COMMIT();
    };

    // -------- prologue: start pipeline; X -> bf16 swizzled; msq --------
    issue(0, 0);
    issue(1, 1);
    if (tid < 64) sMsq[tid] = g_msq[tid];
    for (int q = tid; q < MTOK * 64; q += NTHR) {
        int r = q >> 6, k = (q & 63) * 4;
        int rg = tok0 + r; if (rg >= ntok) rg = ntok - 1;
        float4 v = *reinterpret_cast<const float4*>(&X[(long)rg * 256 + k]);
        uint2 pk; pk.x = packbf(v.x, v.y); pk.y = packbf(v.z, v.w);
        uint32_t off = r * 512 + ((((k >> 3) ^ (r & 7)) << 4) | ((k & 7) << 1));
        *reinterpret_cast<uint2*>(smem + XA_BASE + off) = pk;
    }
    CP_WAIT1();          // chunk 0 resident
    __syncthreads();

    // A-row bases: two m16 tiles per warp
    uint32_t aX[2], aH[2];
    #pragma unroll
    for (int t = 0; t < 2; t++) {
        aX[t] = sb + XA_BASE + (mw * 32 + 16 * t + lrow16) * 512;    // X / feats
        aH[t] = sb + H_BASE  + (mw * 32 + 16 * t + lrow16) * 1024;   // H
    }
    // B-row bases in the two weight buffers (warp's n32: two n16 groups)
    uint32_t bW[2][2];
    #pragma unroll
    for (int b = 0; b < 2; b++)
        #pragma unroll
        for (int g = 0; g < 2; g++)
            bW[b][g] = sb + WB_BASE + b * 16384 + (nw * 32 + 16 * g + brow8) * 256;

    // ================= GEMM1: H = relu(X @ W1 + b1) — 16 chunks (nb, kc) =================
    {
        float acc[2][4][4];
        for (int nb = 0; nb < 8; nb++) {
            #pragma unroll
            for (int t = 0; t < 2; t++)
                #pragma unroll
                for (int j = 0; j < 4; j++)
                    acc[t][j][0] = acc[t][j][1] = acc[t][j][2] = acc[t][j][3] = 0.f;

            for (int kc = 0; kc < 2; kc++) {
                const int q = nb * 2 + kc;
                const int buf = q & 1;
                #pragma unroll
                for (int kk = 0; kk < 8; kk++) {
                    uint32_t a[2][4], b[4][2];
                    uint32_t ksw = ((kc * 16 + 2 * kk + asel) ^ sxr) << 4;
                    uint32_t ksb = ((2 * kk + bsel) ^ sxr) << 4;
                    #pragma unroll
                    for (int t = 0; t < 2; t++) LDSM4(a[t][0], a[t][1], a[t][2], a[t][3], aX[t] + ksw);
                    #pragma unroll
                    for (int g = 0; g < 2; g++) {
                        uint32_t r0, r1, r2, r3;
                        LDSM4(r0, r1, r2, r3, bW[buf][g] + ksb);
                        b[2 * g][0] = r0; b[2 * g][1] = r1;
                        b[2 * g + 1][0] = r2; b[2 * g + 1][1] = r3;
                    }
                    #pragma unroll
                    for (int t = 0; t < 2; t++)
                        #pragma unroll
                        for (int j = 0; j < 4; j++) mma16816(acc[t][j], a[t], b[j]);
                }

                if (kc == 1) {   // epilogue: +b1, relu, stmatrix into H
                    const int n0 = nb * 64 + nw * 32;
                    #pragma unroll
                    for (int g = 0; g < 2; g++) {
                        float2 bc0 = __ldg((const float2*)&b1[n0 + 16 * g + 2 * (lane & 3)]);
                        float2 bc1 = __ldg((const float2*)&b1[n0 + 16 * g + 8 + 2 * (lane & 3)]);
                        #pragma unroll
                        for (int t = 0; t < 2; t++) {
                            int j0 = 2 * g, j1 = 2 * g + 1;
                            uint32_t q0 = packbf(fmaxf(acc[t][j0][0] + bc0.x, 0.f), fmaxf(acc[t][j0][1] + bc0.y, 0.f));
                            uint32_t q1 = packbf(fmaxf(acc[t][j0][2] + bc0.x, 0.f), fmaxf(acc[t][j0][3] + bc0.y, 0.f));
                            uint32_t q2 = packbf(fmaxf(acc[t][j1][0] + bc1.x, 0.f), fmaxf(acc[t][j1][1] + bc1.y, 0.f));
                            uint32_t q3 = packbf(fmaxf(acc[t][j1][2] + bc1.x, 0.f), fmaxf(acc[t][j1][3] + bc1.y, 0.f));
                            uint32_t jc = (uint32_t)(nb * 8 + nw * 4 + 2 * g);
                            STSM4(aH[t] + (((jc + asel) ^ sxr) << 4), q0, q1, q2, q3);
                        }
                    }
                }
                CP_WAIT0();          // chunk q+1 resident
                __syncthreads();
                if (q + 2 < 34) issue(q + 2, buf);   // refill the buffer just consumed
            }
        }
    }

    // ================= GEMM2: F = H @ W2 + b2 — 16 chunks (nc, kc) =================
    float st[2][2], st2[2][2];
    #pragma unroll
    for (int t = 0; t < 2; t++) { st[t][0] = st[t][1] = st2[t][0] = st2[t][1] = 0.f; }

    {
        float acc[2][4][4];
        for (int nc = 0; nc < 4; nc++) {
            #pragma unroll
            for (int t = 0; t < 2; t++)
                #pragma unroll
                for (int j = 0; j < 4; j++)
                    acc[t][j][0] = acc[t][j][1] = acc[t][j][2] = acc[t][j][3] = 0.f;

            for (int kc = 0; kc < 4; kc++) {
                const int q = 16 + nc * 4 + kc;
                const int buf = q & 1;
                #pragma unroll
                for (int kk = 0; kk < 8; kk++) {
                    uint32_t a[2][4], b[4][2];
                    uint32_t ksw = ((kc * 16 + 2 * kk + asel) ^ sxr) << 4;
                    uint32_t ksb = ((2 * kk + bsel) ^ sxr) << 4;
                    #pragma unroll
                    for (int t = 0; t < 2; t++) LDSM4(a[t][0], a[t][1], a[t][2], a[t][3], aH[t] + ksw);
                    #pragma unroll
                    for (int g = 0; g < 2; g++) {
                        uint32_t r0, r1, r2, r3;
                        LDSM4(r0, r1, r2, r3, bW[buf][g] + ksb);
                        b[2 * g][0] = r0; b[2 * g][1] = r1;
                        b[2 * g + 1][0] = r2; b[2 * g + 1][1] = r3;
                    }
                    #pragma unroll
                    for (int t = 0; t < 2; t++)
                        #pragma unroll
                        for (int j = 0; j < 4; j++) mma16816(acc[t][j], a[t], b[j]);
                }

                if (kc == 3) {   // epilogue: +b2, stats, raw F -> XA
                    const int n0 = nc * 64 + nw * 32;
                    #pragma unroll
                    for (int g = 0; g < 2; g++) {
                        float2 bc0 = __ldg((const float2*)&b2[n0 + 16 * g + 2 * (lane & 3)]);
                        float2 bc1 = __ldg((const float2*)&b2[n0 + 16 * g + 8 + 2 * (lane & 3)]);
                        #pragma unroll
                        for (int t = 0; t < 2; t++) {
                            int j0 = 2 * g, j1 = 2 * g + 1;
                            float vA0 = acc[t][j0][0] + bc0.x, vA1 = acc[t][j0][1] + bc0.y;
                            float vB0 = acc[t][j0][2] + bc0.x, vB1 = acc[t][j0][3] + bc0.y;
                            float vA2 = acc[t][j1][0] + bc1.x, vA3 = acc[t][j1][1] + bc1.y;
                            float vB2 = acc[t][j1][2] + bc1.x, vB3 = acc[t][j1][3] + bc1.y;
                            st[t][0]  += vA0 + vA1 + vA2 + vA3;
                            st2[t][0] += vA0 * vA0 + vA1 * vA1 + vA2 * vA2 + vA3 * vA3;
                            st[t][1]  += vB0 + vB1 + vB2 + vB3;
                            st2[t][1] += vB0 * vB0 + vB1 * vB1 + vB2 * vB2 + vB3 * vB3;
                            uint32_t q0 = packbf(vA0, vA1), q1 = packbf(vB0, vB1);
                            uint32_t q2 = packbf(vA2, vA3), q3 = packbf(vB2, vB3);
                            uint32_t jc = (uint32_t)(nc * 8 + nw * 4 + 2 * g);
                            STSM4(aX[t] + (((jc + asel) ^ sxr) << 4), q0, q1, q2, q3);
                        }
                    }
                }
                CP_WAIT0();
                __syncthreads();
                if (q + 2 < 34) issue(q + 2, buf);
            }
        }
    }

    // -------- finalize LN stats --------
    {
        #pragma unroll
        for (int t = 0; t < 2; t++)
            #pragma unroll
            for (int h = 0; h < 2; h++) {
                float s = st[t][h], s2 = st2[t][h];
                s  += __shfl_xor_sync(0xffffffffu, s, 1);  s  += __shfl_xor_sync(0xffffffffu, s, 2);
                s2 += __shfl_xor_sync(0xffffffffu, s2, 1); s2 += __shfl_xor_sync(0xffffffffu, s2, 2);
                if ((lane & 3) == 0) {
                    int r = mw * 32 + 16 * t + 8 * h + (lane >> 2);
                    float m = s * (1.f / 256.f);
                    float v = s2 * (1.f / 256.f) - m * m;
                    sMean[r] = m; sRstd[r] = rsqrtf(v + 1e-5f);
                }
            }
        __syncthreads();
    }

    // -------- normalization pass over feats (bf16 in XA) --------
    {
        int row = tid >> 1, half = tid & 1;
        float mean_r = sMean[row], rstd_r = sRstd[row];
        float fp = 0.f;
        int sxrow = row & 7;
        #pragma unroll
        for (int cc = 0; cc < 16; cc++) {
            int chunk = half * 16 + cc;
            char* p = smem + XA_BASE + row * 512 + ((chunk ^ sxrow) << 4);
            uint4 v = *reinterpret_cast<uint4*>(p);
            uint32_t* vp = reinterpret_cast<uint32_t*>(&v);
            int col0 = chunk * 8;
            float4 g0 = __ldg((const float4*)&lng[col0]);
            float4 g1 = __ldg((const float4*)&lng[col0 + 4]);
            float4 e0 = __ldg((const float4*)&lnb[col0]);
            float4 e1 = __ldg((const float4*)&lnb[col0 + 4]);
            float gg[8] = {g0.x, g0.y, g0.z, g0.w, g1.x, g1.y, g1.z, g1.w};
            float ee[8] = {e0.x, e0.y, e0.z, e0.w, e1.x, e1.y, e1.z, e1.w};
            #pragma unroll
            for (int qq = 0; qq < 4; qq++) {
                __nv_bfloat162 pr = *reinterpret_cast<__nv_bfloat162*>(&vp[qq]);
                float lo = __bfloat162float(pr.x), hi = __bfloat162float(pr.y);
                lo = (lo - mean_r) * rstd_r * gg[2 * qq] + ee[2 * qq];
                hi = (hi - mean_r) * rstd_r * gg[2 * qq + 1] + ee[2 * qq + 1];
                fp += lo * lo + hi * hi;
                vp[qq] = packbf(lo, hi);
            }
            *reinterpret_cast<uint4*>(p) = v;
        }
        fp += __shfl_xor_sync(0xffffffffu, fp, 1);
        if (!half) sFsq[row] = fp;
        CP_WAIT0();          // chunk 33 (Memt hi) resident
        __syncthreads();
    }

    // ================= GEMM3: dots = feats @ Mem^T (Memt in both buffers) =================
    {
        float acc[2][4][4];
        #pragma unroll
        for (int t = 0; t < 2; t++)
            #pragma unroll
            for (int j = 0; j < 4; j++)
                acc[t][j][0] = acc[t][j][1] = acc[t][j][2] = acc[t][j][3] = 0.f;

        #pragma unroll
        for (int kk = 0; kk < 16; kk++) {
            const int buf = kk >> 3;
            uint32_t a[2][4], b[4][2];
            uint32_t ksw = ((2 * kk + asel) ^ sxr) << 4;
            uint32_t ksb = ((2 * (kk & 7) + bsel) ^ sxr) << 4;
            #pragma unroll
            for (int t = 0; t < 2; t++) LDSM4(a[t][0], a[t][1], a[t][2], a[t][3], aX[t] + ksw);
            #pragma unroll
            for (int g = 0; g < 2; g++) {
                uint32_t r0, r1, r2, r3;
                LDSM4(r0, r1, r2, r3, bW[buf][g] + ksb);
                b[2 * g][0] = r0; b[2 * g][1] = r1;
                b[2 * g + 1][0] = r2; b[2 * g + 1][1] = r3;
            }
            #pragma unroll
            for (int t = 0; t < 2; t++)
                #pragma unroll
                for (int j = 0; j < 4; j++) mma16816(acc[t][j], a[t], b[j]);
        }

        // distances -> smem (H region, stride 272B)
        #pragma unroll
        for (int t = 0; t < 2; t++) {
            int rA = mw * 32 + 16 * t + (lane >> 2), rB = rA + 8;
            float fA = sFsq[rA], fB = sFsq[rB];
            #pragma unroll
            for (int j = 0; j < 4; j++) {
                int g = j >> 1, u = j & 1;
                int c0 = nw * 32 + 16 * g + 8 * u + 2 * (lane & 3);
                float mq0 = sMsq[c0], mq1 = sMsq[c0 + 1];
                float2 dA, dB;
                dA.x = sqrtf(fmaxf(fA + mq0 - 2.f * acc[t][j][0], 0.f));
                dA.y = sqrtf(fmaxf(fA + mq1 - 2.f * acc[t][j][1], 0.f));
                dB.x = sqrtf(fmaxf(fB + mq0 - 2.f * acc[t][j][2], 0.f));
                dB.y = sqrtf(fmaxf(fB + mq1 - 2.f * acc[t][j][3], 0.f));
                *reinterpret_cast<float2*>(smem + H_BASE + rA * DIST_STRIDE + c0 * 4) = dA;
                *reinterpret_cast<float2*>(smem + H_BASE + rB * DIST_STRIDE + c0 * 4) = dB;
            }
        }
        __syncthreads();
    }

    // ================= top-5 + sigmoid =================
    if (tid < MTOK) {
        const float* dr = reinterpret_cast<const float*>(smem + H_BASE + tid * DIST_STRIDE);
        float b0 = FLT_MAX, bq1 = FLT_MAX, bq2 = FLT_MAX, bq3 = FLT_MAX, bq4 = FLT_MAX;
        #pragma unroll
        for (int m = 0; m < 50; m++) {
            float v = dr[m];
            if (v < bq4) {
                bq4 = v;
                if (bq4 < bq3) { float x = bq3; bq3 = bq4; bq4 = x; }
                if (bq3 < bq2) { float x = bq2; bq2 = bq3; bq3 = x; }
                if (bq2 < bq1) { float x = bq1; bq1 = bq2; bq2 = x; }
                if (bq1 < b0)  { float x = b0;  b0  = bq1; bq1 = x; }
            }
        }
        float avg = (b0 + bq1 + bq2 + bq3 + bq4) * 0.2f;
        int tg = tok0 + tid;
        if (tg < ntok) out[tg] = 1.f / (1.f + expf(1.f - avg));
    }
}

// ================= launch =================
extern "C" void kernel_launch(void* const* d_in, const int* in_sizes, int n_in,
                              void* d_out, int out_size) {
    const float* X   = (const float*)d_in[0];
    const float* Mem = (const float*)d_in[1];
    const float* W1  = (const float*)d_in[2];
    const float* b1  = (const float*)d_in[3];
    const float* W2  = (const float*)d_in[4];
    const float* b2  = (const float*)d_in[5];
    const float* g   = (const float*)d_in[6];
    const float* be  = (const float*)d_in[7];
    float* out = (float*)d_out;

    int ntok = out_size;
    int grid = (ntok + MTOK - 1) / MTOK;

    prep_weights<<<1088, 256>>>(W1, W2, Mem);
    prep_msq<<<64, 32>>>(Mem);

    cudaFuncSetAttribute(ipm_mma, cudaFuncAttributeMaxDynamicSharedMemorySize, SMEM_BYTES);
    ipm_mma<<<grid, NTHR, SMEM_BYTES>>>(X, b1, b2, g, be, out, ntok);
}

// round 6
// speedup vs baseline: 8.5642x; 1.0004x over previous
#include <cuda_runtime.h>
#include <cuda_bf16.h>
#include <math.h>
#include <float.h>
#include <stdint.h>

// ================= geometry =================
#define NTHR 256
#define MTOK 128

// smem byte map
#define XA_BASE   0          // X / raw-F bf16 image: 128 rows x 512B (64 KB)
#define H_BASE    65536      // H bf16 image: 128 rows x 1024B (128 KB); later dists+stats
#define WB_BASE   196608     // 2 x 16 KB weight chunk buffers
#define GG2_BASE  229376     // 256 f32: gamma^2
#define GB_BASE   230400     // 256 f32: gamma*beta
#define SMEM_BYTES 231424

// inside H region, used AFTER GEMM2 is done
#define PART_OFF  (H_BASE + 40960)   // [128][2][5] f32 partial sums
#define MU_OFF    (H_BASE + 46080)   // 128 f32
#define R_OFF     (H_BASE + 46592)   // 128 f32
#define FSQ_OFF   (H_BASE + 47104)   // 128 f32
#define GM_OFF    (H_BASE + 47616)   // 64 f32
#define CM_OFF    (H_BASE + 47872)   // 64 f32

#define DIST_STRIDE 272      // bytes per dist row (dists live at H_BASE, rows < 34.5KB)

// device scratch: pre-swizzled bf16 weight images, 16KB chunks
__device__ uint4 g_W1t[16384];   // 16 chunks (nb*4+kc): n128 x k64, 128B rows
__device__ uint4 g_W2t[16384];   // 16 chunks (nc*8+kc): n128 x k64, 128B rows
__device__ uint4 g_Memt[2048];   // 2 chunks (kc): 64 rows x k128, 256B rows, gamma-scaled
__device__ float g_gm[64];       // sum(gamma*m)
__device__ float g_cM[64];       // sum(m^2) - 2*sum(beta*m)
__device__ float g_cons[3];      // Sbb, Sgb, Sgg

// ================= asm helpers =================
__device__ __forceinline__ uint32_t smem_u32(const void* p) {
    uint32_t a;
    asm("{ .reg .u64 t; cvta.to.shared.u64 t, %1; cvt.u32.u64 %0, t; }" : "=r"(a) : "l"(p));
    return a;
}
#define LDSM4(r0, r1, r2, r3, a) \
    asm volatile("ldmatrix.sync.aligned.m8n8.x4.shared.b16 {%0,%1,%2,%3}, [%4];" \
        : "=r"(r0), "=r"(r1), "=r"(r2), "=r"(r3) : "r"(a))
#define STSM4(a, r0, r1, r2, r3) \
    asm volatile("stmatrix.sync.aligned.m8n8.x4.shared.b16 [%0], {%1,%2,%3,%4};" \
        :: "r"(a), "r"(r0), "r"(r1), "r"(r2), "r"(r3) : "memory")
#define CP16(dst, src) \
    asm volatile("cp.async.cg.shared.global [%0], [%1], 16;" :: "r"(dst), "l"(src))
#define CP_COMMIT() asm volatile("cp.async.commit_group;" ::: "memory")
#define CP_WAIT0()  asm volatile("cp.async.wait_group 0;" ::: "memory")
#define CP_WAIT1()  asm volatile("cp.async.wait_group 1;" ::: "memory")

__device__ __forceinline__ void mma16816(float* d, const uint32_t* a, const uint32_t* b) {
    asm volatile(
        "mma.sync.aligned.m16n8k16.row.col.f32.bf16.bf16.f32 "
        "{%0,%1,%2,%3}, {%4,%5,%6,%7}, {%8,%9}, {%0,%1,%2,%3};"
        : "+f"(d[0]), "+f"(d[1]), "+f"(d[2]), "+f"(d[3])
        : "r"(a[0]), "r"(a[1]), "r"(a[2]), "r"(a[3]), "r"(b[0]), "r"(b[1]));
}
__device__ __forceinline__ uint32_t packbf(float lo, float hi) {
    __nv_bfloat162 p = __floats2bfloat162_rn(lo, hi);
    return *reinterpret_cast<uint32_t*>(&p);
}

// ================= prep kernels =================
__global__ void prep_weights(const float* __restrict__ W1, const float* __restrict__ W2,
                             const float* __restrict__ Mem, const float* __restrict__ lng) {
    int e = blockIdx.x * 256 + threadIdx.x;
    if (e < 131072) {                               // W1: [k=256][n=512]
        int n = e >> 8, k = e & 255;
        int q = (n >> 7) * 4 + (k >> 6);
        int np = n & 127, kl = k & 63;
        uint32_t off = (uint32_t)q * 16384u + np * 128u
                     + (uint32_t)((((kl >> 3) ^ (np & 7)) << 4) | ((kl & 7) << 1));
        *((__nv_bfloat16*)((char*)g_W1t + off)) = __float2bfloat16(W1[k * 512 + n]);
    } else if (e < 262144) {                        // W2: [k=512][n=256]
        int x = e - 131072;
        int n = x >> 9, k = x & 511;
        int q = (n >> 7) * 8 + (k >> 6);
        int np = n & 127, kl = k & 63;
        uint32_t off = (uint32_t)q * 16384u + np * 128u
                     + (uint32_t)((((kl >> 3) ^ (np & 7)) << 4) | ((kl & 7) << 1));
        *((__nv_bfloat16*)((char*)g_W2t + off)) = __float2bfloat16(W2[k * 256 + n]);
    } else if (e < 278528) {                        // Memt: 64 rows (50 real) x k256, gamma-scaled
        int x = e - 262144;
        int m = x >> 8, k = x & 255;
        float v = (m < 50) ? Mem[m * 256 + k] * lng[k] : 0.f;
        int q = k >> 7, kl = k & 127;
        int c = kl >> 3;
        int cp = (c & 8) | ((c & 7) ^ (m & 7));
        uint32_t off = (uint32_t)q * 16384u + m * 256u
                     + (uint32_t)((cp << 4) | ((kl & 7) << 1));
        *((__nv_bfloat16*)((char*)g_Memt + off)) = __float2bfloat16(v);
    }
}

__global__ void prep_red(const float* __restrict__ Mem, const float* __restrict__ lng,
                         const float* __restrict__ lnb) {   // <<<65, 32>>>
    int b = blockIdx.x, lane = threadIdx.x;
    if (b < 64) {
        float msq = 0.f, gm = 0.f, bm = 0.f;
        if (b < 50) {
            #pragma unroll
            for (int j = 0; j < 8; j++) {
                int c = lane + 32 * j;
                float mv = Mem[b * 256 + c];
                msq += mv * mv; gm += lng[c] * mv; bm += lnb[c] * mv;
            }
        }
        #pragma unroll
        for (int o = 16; o; o >>= 1) {
            msq += __shfl_xor_sync(0xffffffffu, msq, o);
            gm  += __shfl_xor_sync(0xffffffffu, gm,  o);
            bm  += __shfl_xor_sync(0xffffffffu, bm,  o);
        }
        if (lane == 0) { g_gm[b] = gm; g_cM[b] = msq - 2.f * bm; }
    } else {
        float sbb = 0.f, sgb = 0.f, sgg = 0.f;
        #pragma unroll
        for (int j = 0; j < 8; j++) {
            int c = lane + 32 * j;
            float gv = lng[c], bv = lnb[c];
            sgg += gv * gv; sgb += gv * bv; sbb += bv * bv;
        }
        #pragma unroll
        for (int o = 16; o; o >>= 1) {
            sbb += __shfl_xor_sync(0xffffffffu, sbb, o);
            sgb += __shfl_xor_sync(0xffffffffu, sgb, o);
            sgg += __shfl_xor_sync(0xffffffffu, sgg, o);
        }
        if (lane == 0) { g_cons[0] = sbb; g_cons[1] = sgb; g_cons[2] = sgg; }
    }
}

// chunk source: 0..15 W1, 16..31 W2, 32..33 Mem
__device__ __forceinline__ const uint4* chunk_src(int q) {
    return (q < 16) ? (g_W1t + q * 1024)
         : (q < 32) ? (g_W2t + (q - 16) * 1024)
                    : (g_Memt + (q - 32) * 1024);
}

// ================= main fused kernel =================
__global__ __launch_bounds__(NTHR, 1)
void ipm_mma(const float* __restrict__ X,
             const float* __restrict__ b1, const float* __restrict__ b2,
             const float* __restrict__ lng, const float* __restrict__ lnb,
             float* __restrict__ out, int ntok)
{
    extern __shared__ __align__(1024) char smem[];
    const uint32_t sb = smem_u32(smem);
    const int tid  = threadIdx.x;
    const int lane = tid & 31;
    const int w    = tid >> 5;
    const int mw   = w & 3;            // M group (32 rows)
    const int nw   = w >> 2;           // N group (64 cols in G1/G2, 32 in G3)
    const int tok0 = blockIdx.x * MTOK;

    float* sGg2 = reinterpret_cast<float*>(smem + GG2_BASE);
    float* sGb  = reinterpret_cast<float*>(smem + GB_BASE);
    float* sMu  = reinterpret_cast<float*>(smem + MU_OFF);
    float* sR   = reinterpret_cast<float*>(smem + R_OFF);
    float* sFsq = reinterpret_cast<float*>(smem + FSQ_OFF);
    float* sGm  = reinterpret_cast<float*>(smem + GM_OFF);
    float* sCM  = reinterpret_cast<float*>(smem + CM_OFF);

    const uint32_t lrow16 = lane & 15;
    const uint32_t asel   = lane >> 4;
    const uint32_t sxr    = lane & 7;
    const uint32_t bsel   = (lane >> 3) & 1;
    const uint32_t brow8  = (lane & 7) + ((lane >> 4) << 3);

    const uint32_t cpdst = sb + WB_BASE + tid * 16;
    auto issue = [&](int q, int b) {
        const uint4* src = chunk_src(q) + tid;
        uint32_t d = cpdst + (uint32_t)b * 16384u;
        #pragma unroll
        for (int u = 0; u < 4; u++) CP16(d + u * 4096u, src + u * 256);
        CP_COMMIT();
    };

    // -------- prologue --------
    issue(0, 0);
    issue(1, 1);
    {
        float gv = lng[tid], bv = lnb[tid];
        sGg2[tid] = gv * gv;
        sGb[tid]  = gv * bv;
    }
    for (int q = tid; q < MTOK * 64; q += NTHR) {
        int r = q >> 6, k = (q & 63) * 4;
        int rg = tok0 + r; if (rg >= ntok) rg = ntok - 1;
        float4 v = *reinterpret_cast<const float4*>(&X[(long)rg * 256 + k]);
        uint2 pk; pk.x = packbf(v.x, v.y); pk.y = packbf(v.z, v.w);
        uint32_t off = r * 512 + ((((k >> 3) ^ (r & 7)) << 4) | ((k & 7) << 1));
        *reinterpret_cast<uint2*>(smem + XA_BASE + off) = pk;
    }
    CP_WAIT1();
    __syncthreads();

    // A-row bases: two m16 tiles per warp (m32)
    uint32_t aX[2], aH[2];
    #pragma unroll
    for (int t = 0; t < 2; t++) {
        aX[t] = sb + XA_BASE + (mw * 32 + 16 * t + lrow16) * 512;
        aH[t] = sb + H_BASE  + (mw * 32 + 16 * t + lrow16) * 1024;
    }
    // B-row bases: warp's n64 in weight chunks (128B rows)
    uint32_t bW[2][4];
    #pragma unroll
    for (int b = 0; b < 2; b++)
        #pragma unroll
        for (int g = 0; g < 4; g++)
            bW[b][g] = sb + WB_BASE + b * 16384 + (nw * 64 + 16 * g + brow8) * 128;
    // GEMM3 B-row bases: warp's n32 in Mem chunks (256B rows)
    uint32_t bM[2][2];
    #pragma unroll
    for (int b = 0; b < 2; b++)
        #pragma unroll
        for (int g = 0; g < 2; g++)
            bM[b][g] = sb + WB_BASE + b * 16384 + (nw * 32 + 16 * g + brow8) * 256;

    // ================= GEMM1: H = relu(X @ W1 + b1) =================
    {
        float acc[2][8][4];
        for (int nb = 0; nb < 4; nb++) {
            #pragma unroll
            for (int t = 0; t < 2; t++)
                #pragma unroll
                for (int j = 0; j < 8; j++)
                    acc[t][j][0] = acc[t][j][1] = acc[t][j][2] = acc[t][j][3] = 0.f;

            for (int kc = 0; kc < 4; kc++) {
                const int q = nb * 4 + kc;
                const int buf = q & 1;
                #pragma unroll
                for (int kk = 0; kk < 4; kk++) {
                    uint32_t a[2][4], bfr[8][2];
                    uint32_t ksw = (((uint32_t)(kc * 8 + 2 * kk) + asel) ^ sxr) << 4;
                    uint32_t ksb = (((uint32_t)(2 * kk) + bsel) ^ sxr) << 4;
                    #pragma unroll
                    for (int t = 0; t < 2; t++) LDSM4(a[t][0], a[t][1], a[t][2], a[t][3], aX[t] + ksw);
                    #pragma unroll
                    for (int g = 0; g < 4; g++) {
                        uint32_t r0, r1, r2, r3;
                        LDSM4(r0, r1, r2, r3, bW[buf][g] + ksb);
                        bfr[2 * g][0] = r0; bfr[2 * g][1] = r1;
                        bfr[2 * g + 1][0] = r2; bfr[2 * g + 1][1] = r3;
                    }
                    #pragma unroll
                    for (int t = 0; t < 2; t++)
                        #pragma unroll
                        for (int j = 0; j < 8; j++) mma16816(acc[t][j], a[t], bfr[j]);
                }

                if (kc == 3) {   // epilogue: +b1, relu -> H
                    const int n0 = nb * 128 + nw * 64;
                    #pragma unroll
                    for (int g = 0; g < 4; g++) {
                        float2 bc0 = __ldg((const float2*)&b1[n0 + 16 * g + 2 * (lane & 3)]);
                        float2 bc1 = __ldg((const float2*)&b1[n0 + 16 * g + 8 + 2 * (lane & 3)]);
                        #pragma unroll
                        for (int t = 0; t < 2; t++) {
                            int j0 = 2 * g, j1 = 2 * g + 1;
                            uint32_t q0 = packbf(fmaxf(acc[t][j0][0] + bc0.x, 0.f), fmaxf(acc[t][j0][1] + bc0.y, 0.f));
                            uint32_t q1 = packbf(fmaxf(acc[t][j0][2] + bc0.x, 0.f), fmaxf(acc[t][j0][3] + bc0.y, 0.f));
                            uint32_t q2 = packbf(fmaxf(acc[t][j1][0] + bc1.x, 0.f), fmaxf(acc[t][j1][1] + bc1.y, 0.f));
                            uint32_t q3 = packbf(fmaxf(acc[t][j1][2] + bc1.x, 0.f), fmaxf(acc[t][j1][3] + bc1.y, 0.f));
                            uint32_t jc = (uint32_t)(nb * 16 + nw * 8 + 2 * g);
                            STSM4(aH[t] + (((jc + asel) ^ sxr) << 4), q0, q1, q2, q3);
                        }
                    }
                }
                CP_WAIT0();
                __syncthreads();
                if (q + 2 < 34) issue(q + 2, buf);
            }
        }
    }

    // ================= GEMM2: rawF = H @ W2 + b2 (5-sum stats on the fly) =================
    float st[2][2][5];   // [t][rh][ S1, S2, A2, A1g, C1 ]
    #pragma unroll
    for (int t = 0; t < 2; t++)
        #pragma unroll
        for (int h = 0; h < 2; h++)
            #pragma unroll
            for (int i = 0; i < 5; i++) st[t][h][i] = 0.f;

    {
        float acc[2][8][4];
        for (int nc = 0; nc < 2; nc++) {
            #pragma unroll
            for (int t = 0; t < 2; t++)
                #pragma unroll
                for (int j = 0; j < 8; j++)
                    acc[t][j][0] = acc[t][j][1] = acc[t][j][2] = acc[t][j][3] = 0.f;

            for (int kc = 0; kc < 8; kc++) {
                const int q = 16 + nc * 8 + kc;
                const int buf = q & 1;
                #pragma unroll
                for (int kk = 0; kk < 4; kk++) {
                    uint32_t a[2][4], bfr[8][2];
                    uint32_t ksw = (((uint32_t)(kc * 8 + 2 * kk) + asel) ^ sxr) << 4;
                    uint32_t ksb = (((uint32_t)(2 * kk) + bsel) ^ sxr) << 4;
                    #pragma unroll
                    for (int t = 0; t < 2; t++) LDSM4(a[t][0], a[t][1], a[t][2], a[t][3], aH[t] + ksw);
                    #pragma unroll
                    for (int g = 0; g < 4; g++) {
                        uint32_t r0, r1, r2, r3;
                        LDSM4(r0, r1, r2, r3, bW[buf][g] + ksb);
                        bfr[2 * g][0] = r0; bfr[2 * g][1] = r1;
                        bfr[2 * g + 1][0] = r2; bfr[2 * g + 1][1] = r3;
                    }
                    #pragma unroll
                    for (int t = 0; t < 2; t++)
                        #pragma unroll
                        for (int j = 0; j < 8; j++) mma16816(acc[t][j], a[t], bfr[j]);
                }

                if (kc == 7) {   // epilogue: +b2, stats, raw F -> XA
                    const int n0 = nc * 128 + nw * 64;
                    #pragma unroll
                    for (int g = 0; g < 4; g++) {
                        const int c00 = n0 + 16 * g + 2 * (lane & 3);
                        const int c10 = c00 + 8;
                        float2 bc0 = __ldg((const float2*)&b2[c00]);
                        float2 bc1 = __ldg((const float2*)&b2[c10]);
                        float2 G0 = *reinterpret_cast<float2*>(sGg2 + c00);
                        float2 G1 = *reinterpret_cast<float2*>(sGg2 + c10);
                        float2 E0 = *reinterpret_cast<float2*>(sGb + c00);
                        float2 E1 = *reinterpret_cast<float2*>(sGb + c10);
                        #pragma unroll
                        for (int t = 0; t < 2; t++) {
                            int j0 = 2 * g, j1 = 2 * g + 1;
                            float v00 = acc[t][j0][0] + bc0.x, v01 = acc[t][j0][1] + bc0.y;
                            float v02 = acc[t][j0][2] + bc0.x, v03 = acc[t][j0][3] + bc0.y;
                            float v10 = acc[t][j1][0] + bc1.x, v11 = acc[t][j1][1] + bc1.y;
                            float v12 = acc[t][j1][2] + bc1.x, v13 = acc[t][j1][3] + bc1.y;
                            // rh=0 (row rA)
                            st[t][0][0] += v00 + v01 + v10 + v11;
                            st[t][0][1] += v00 * v00 + v01 * v01 + v10 * v10 + v11 * v11;
                            st[t][0][2] += G0.x * v00 * v00 + G0.y * v01 * v01 + G1.x * v10 * v10 + G1.y * v11 * v11;
                            st[t][0][3] += G0.x * v00 + G0.y * v01 + G1.x * v10 + G1.y * v11;
                            st[t][0][4] += E0.x * v00 + E0.y * v01 + E1.x * v10 + E1.y * v11;
                            // rh=1 (row rA+8)
                            st[t][1][0] += v02 + v03 + v12 + v13;
                            st[t][1][1] += v02 * v02 + v03 * v03 + v12 * v12 + v13 * v13;
                            st[t][1][2] += G0.x * v02 * v02 + G0.y * v03 * v03 + G1.x * v12 * v12 + G1.y * v13 * v13;
                            st[t][1][3] += G0.x * v02 + G0.y * v03 + G1.x * v12 + G1.y * v13;
                            st[t][1][4] += E0.x * v02 + E0.y * v03 + E1.x * v12 + E1.y * v13;

                            uint32_t q0 = packbf(v00, v01), q1 = packbf(v02, v03);
                            uint32_t q2 = packbf(v10, v11), q3 = packbf(v12, v13);
                            uint32_t jc = (uint32_t)(nc * 16 + nw * 8 + 2 * g);
                            STSM4(aX[t] + (((jc + asel) ^ sxr) << 4), q0, q1, q2, q3);
                        }
                    }
                }
                CP_WAIT0();
                __syncthreads();
                if (q + 2 < 34) issue(q + 2, buf);
            }
        }
    }

    // -------- stats: quad-reduce, partials to smem, combine --------
    {
        #pragma unroll
        for (int t = 0; t < 2; t++)
            #pragma unroll
            for (int h = 0; h < 2; h++)
                #pragma unroll
                for (int i = 0; i < 5; i++) {
                    float s = st[t][h][i];
                    s += __shfl_xor_sync(0xffffffffu, s, 1);
                    s += __shfl_xor_sync(0xffffffffu, s, 2);
                    st[t][h][i] = s;
                }
        if ((lane & 3) == 0) {
            #pragma unroll
            for (int t = 0; t < 2; t++)
                #pragma unroll
                for (int h = 0; h < 2; h++) {
                    int row = mw * 32 + 16 * t + 8 * h + (lane >> 2);
                    float* p = reinterpret_cast<float*>(smem + PART_OFF) + (row * 2 + nw) * 5;
                    #pragma unroll
                    for (int i = 0; i < 5; i++) p[i] = st[t][h][i];
                }
        }
        __syncthreads();

        if (tid < MTOK) {
            const float* p0 = reinterpret_cast<const float*>(smem + PART_OFF) + (tid * 2) * 5;
            float S1 = p0[0] + p0[5], S2 = p0[1] + p0[6], A2 = p0[2] + p0[7];
            float A1g = p0[3] + p0[8], C1 = p0[4] + p0[9];
            float Sbb = __ldg(&g_cons[0]), Sgb = __ldg(&g_cons[1]), Sgg = __ldg(&g_cons[2]);
            float mu = S1 * (1.f / 256.f);
            float var = S2 * (1.f / 256.f) - mu * mu;
            float r = rsqrtf(var + 1e-5f);
            float fsq = r * r * A2 + 2.f * r * C1 - 2.f * mu * r * r * A1g
                      + Sbb - 2.f * mu * r * Sgb + mu * mu * r * r * Sgg;
            sMu[tid] = mu; sR[tid] = r; sFsq[tid] = fsq;
        }
        if (tid < 64) { sGm[tid] = __ldg(&g_gm[tid]); sCM[tid] = __ldg(&g_cM[tid]); }
        CP_WAIT0();          // Mem chunks resident
        __syncthreads();
    }

    // ================= GEMM3: D = rawF @ (gamma.Mem)^T =================
    {
        float acc[2][4][4];
        #pragma unroll
        for (int t = 0; t < 2; t++)
            #pragma unroll
            for (int j = 0; j < 4; j++)
                acc[t][j][0] = acc[t][j][1] = acc[t][j][2] = acc[t][j][3] = 0.f;

        #pragma unroll
        for (int kk = 0; kk < 16; kk++) {
            const int buf = kk >> 3;
            const int kj = kk & 7;
            uint32_t a[2][4], bfr[4][2];
            uint32_t ksw = (((uint32_t)(2 * kk) + asel) ^ sxr) << 4;
            uint32_t c = (uint32_t)(2 * kj) + bsel;
            uint32_t cp = (c & 8u) | ((c & 7u) ^ sxr);
            uint32_t ksb = cp << 4;
            #pragma unroll
            for (int t = 0; t < 2; t++) LDSM4(a[t][0], a[t][1], a[t][2], a[t][3], aX[t] + ksw);
            #pragma unroll
            for (int g = 0; g < 2; g++) {
                uint32_t r0, r1, r2, r3;
                LDSM4(r0, r1, r2, r3, bM[buf][g] + ksb);
                bfr[2 * g][0] = r0; bfr[2 * g][1] = r1;
                bfr[2 * g + 1][0] = r2; bfr[2 * g + 1][1] = r3;
            }
            #pragma unroll
            for (int t = 0; t < 2; t++)
                #pragma unroll
                for (int j = 0; j < 4; j++) mma16816(acc[t][j], a[t], bfr[j]);
        }

        // distances: d^2 = fsq + cM + 2*r*(mu*gm - D)
        #pragma unroll
        for (int t = 0; t < 2; t++) {
            int rA = mw * 32 + 16 * t + (lane >> 2), rB = rA + 8;
            float fA = sFsq[rA], rrA = sR[rA], muA = sMu[rA];
            float fB = sFsq[rB], rrB = sR[rB], muB = sMu[rB];
            #pragma unroll
            for (int j = 0; j < 4; j++) {
                int g = j >> 1, u = j & 1;
                int c0 = nw * 32 + 16 * g + 8 * u + 2 * (lane & 3);
                float gm0 = sGm[c0], gm1 = sGm[c0 + 1];
                float cm0 = sCM[c0], cm1 = sCM[c0 + 1];
                float2 dA, dB;
                dA.x = sqrtf(fmaxf(fA + cm0 + 2.f * rrA * (muA * gm0 - acc[t][j][0]), 0.f));
                dA.y = sqrtf(fmaxf(fA + cm1 + 2.f * rrA * (muA * gm1 - acc[t][j][1]), 0.f));
                dB.x = sqrtf(fmaxf(fB + cm0 + 2.f * rrB * (muB * gm0 - acc[t][j][2]), 0.f));
                dB.y = sqrtf(fmaxf(fB + cm1 + 2.f * rrB * (muB * gm1 - acc[t][j][3]), 0.f));
                *reinterpret_cast<float2*>(smem + H_BASE + rA * DIST_STRIDE + c0 * 4) = dA;
                *reinterpret_cast<float2*>(smem + H_BASE + rB * DIST_STRIDE + c0 * 4) = dB;
            }
        }
        __syncthreads();
    }

    // ================= top-5 + sigmoid =================
    if (tid < MTOK) {
        const float* dr = reinterpret_cast<const float*>(smem + H_BASE + tid * DIST_STRIDE);
        float b0 = FLT_MAX, bq1 = FLT_MAX, bq2 = FLT_MAX, bq3 = FLT_MAX, bq4 = FLT_MAX;
        #pragma unroll
        for (int m = 0; m < 50; m++) {
            float v = dr[m];
            if (v < bq4) {
                bq4 = v;
                if (bq4 < bq3) { float x = bq3; bq3 = bq4; bq4 = x; }
                if (bq3 < bq2) { float x = bq2; bq2 = bq3; bq3 = x; }
                if (bq2 < bq1) { float x = bq1; bq1 = bq2; bq2 = x; }
                if (bq1 < b0)  { float x = b0;  b0  = bq1; bq1 = x; }
            }
        }
        float avg = (b0 + bq1 + bq2 + bq3 + bq4) * 0.2f;
        int tg = tok0 + tid;
        if (tg < ntok) out[tg] = 1.f / (1.f + expf(1.f - avg));
    }
}

// ================= launch =================
extern "C" void kernel_launch(void* const* d_in, const int* in_sizes, int n_in,
                              void* d_out, int out_size) {
    const float* X   = (const float*)d_in[0];
    const float* Mem = (const float*)d_in[1];
    const float* W1  = (const float*)d_in[2];
    const float* b1  = (const float*)d_in[3];
    const float* W2  = (const float*)d_in[4];
    const float* b2  = (const float*)d_in[5];
    const float* g   = (const float*)d_in[6];
    const float* be  = (const float*)d_in[7];
    float* out = (float*)d_out;

    int ntok = out_size;
    int grid = (ntok + MTOK - 1) / MTOK;

    prep_weights<<<1088, 256>>>(W1, W2, Mem, g);
    prep_red<<<65, 32>>>(Mem, g, be);

    cudaFuncSetAttribute(ipm_mma, cudaFuncAttributeMaxDynamicSharedMemorySize, SMEM_BYTES);
    ipm_mma<<<grid, NTHR, SMEM_BYTES>>>(X, b1, b2, g, be, out, ntok);
}